// round 12
// baseline (speedup 1.0000x reference)
#include <cuda_runtime.h>
#include <cuda_fp16.h>
#include <cstdint>

#define B_SZ 4
#define DIMC 384
#define L_SEQ 4096
#define D_INNER 768
#define D_STATE 16
#define DT_RANK 24
#define XPN 56
#define M_TOTAL (B_SZ * L_SEQ)      // 16384

// ---------------- scratch (no allocations allowed) ----------------
__device__ float g_xz[(size_t)M_TOTAL * 2 * D_INNER];
__device__ float g_xc[(size_t)M_TOTAL * D_INNER];
__device__ float g_xdbl[(size_t)M_TOTAL * XPN];
__device__ float g_dtv[(size_t)M_TOTAL * D_INNER];

__device__ __half g_xn_h[(size_t)M_TOTAL * DIMC];
__device__ __half g_xc_h[(size_t)M_TOTAL * D_INNER];
__device__ __half g_y_h[(size_t)M_TOTAL * D_INNER];
__device__ __half g_wi_hi[(size_t)2 * D_INNER * DIMC];
__device__ __half g_wi_lo[(size_t)2 * D_INNER * DIMC];
__device__ __half g_wo_hi[(size_t)DIMC * D_INNER];
__device__ __half g_wo_lo[(size_t)DIMC * D_INNER];
__device__ __half g_wx_hi[(size_t)XPN * D_INNER];
__device__ __half g_wx_lo[(size_t)XPN * D_INNER];

// ---------------- small PTX helpers (all base-target, sm_80+) ----------------
__device__ __forceinline__ uint32_t smem_u32(const void* p) {
    uint32_t a;
    asm("{ .reg .u64 t; cvta.to.shared.u64 t, %1; cvt.u32.u64 %0, t; }" : "=r"(a) : "l"(p));
    return a;
}
__device__ __forceinline__ void cpasync16(uint32_t sa, const void* g, int sz) {
    asm volatile("cp.async.cg.shared.global [%0], [%1], 16, %2;" :: "r"(sa), "l"(g), "r"(sz) : "memory");
}
__device__ __forceinline__ void cp_commit() {
    asm volatile("cp.async.commit_group;" ::: "memory");
}
template <int N> __device__ __forceinline__ void cp_wait() {
    asm volatile("cp.async.wait_group %0;" :: "n"(N) : "memory");
}
__device__ __forceinline__ void ldsm4(uint32_t* r, uint32_t addr) {
    asm volatile("ldmatrix.sync.aligned.m8n8.x4.shared.b16 {%0,%1,%2,%3}, [%4];"
                 : "=r"(r[0]), "=r"(r[1]), "=r"(r[2]), "=r"(r[3]) : "r"(addr));
}
__device__ __forceinline__ void mma16816h(float* d, const uint32_t* a, const uint32_t* b) {
    asm volatile(
        "mma.sync.aligned.m16n8k16.row.col.f32.f16.f16.f32 "
        "{%0,%1,%2,%3}, {%4,%5,%6,%7}, {%8,%9}, {%0,%1,%2,%3};"
        : "+f"(d[0]), "+f"(d[1]), "+f"(d[2]), "+f"(d[3])
        : "r"(a[0]), "r"(a[1]), "r"(a[2]), "r"(a[3]), "r"(b[0]), "r"(b[1]));
}

// ---------------- fp16 2-term mma.sync GEMM (256 thr, 2 CTA/SM, 3-stage ring) ----------------
#define LDSROW 40
#define TILE_H (128 * LDSROW)       // 5120 halves
#define STAGE_B (3 * TILE_H * 2)    // 30720 B per stage
#define NST 3
#define MM_SMEM (NST * STAGE_B)     // 92160 B

__global__ __launch_bounds__(256, 2) void mmagemm_kernel(
    const __half* __restrict__ Ah,
    const __half* __restrict__ Bh, const __half* __restrict__ Bl,
    int K, int Nn, float* __restrict__ C, int ldc, int mode) {

    extern __shared__ __align__(16) uint8_t dsm[];
    uint32_t dsm_u = smem_u32(dsm);

    int tid = threadIdx.x;
    int wid = tid >> 5;
    int lane = tid & 31;
    int warp_m = wid & 1;      // 2 warps over m (2*64 = 128)
    int warp_n = wid >> 1;     // 4 warps over n (4*32 = 128)
    int m0 = blockIdx.y * 128;
    int n0 = blockIdx.x * 128;

    float acc[4][4][4];
    #pragma unroll
    for (int mt = 0; mt < 4; mt++)
        #pragma unroll
        for (int nt = 0; nt < 4; nt++)
            #pragma unroll
            for (int q = 0; q < 4; q++) acc[mt][nt][q] = 0.f;

    int nchunks = K >> 5;

    auto load_chunk = [&](int c) {
        int kc = c << 5;
        uint32_t sbase = dsm_u + (c % NST) * STAGE_B;
        #pragma unroll
        for (int i = 0; i < 6; i++) {
            int u = tid + i * 256;
            int tile = u >> 9;      // 0=A, 1=Bh, 2=Bl
            int v = u & 511;
            int row = v >> 2;
            int seg = v & 3;
            uint32_t sa = sbase + (tile * TILE_H + row * LDSROW + seg * 8) * 2;
            const __half* g;
            int sz = 16;
            if (tile == 0) {
                g = Ah + (size_t)(m0 + row) * K + kc + seg * 8;
            } else {
                int r = n0 + row;
                if (r >= Nn) { r = Nn - 1; sz = 0; }
                g = ((tile == 1) ? Bh : Bl) + (size_t)r * K + kc + seg * 8;
            }
            cpasync16(sa, g, sz);
        }
        cp_commit();
    };

    load_chunk(0);

    for (int c = 0; c < nchunks; c++) {
        if (c + 1 < nchunks) { load_chunk(c + 1); cp_wait<1>(); }
        else { cp_wait<0>(); }
        __syncthreads();   // single barrier per chunk (NST >= depth+2)

        uint32_t base = dsm_u + (c % NST) * STAGE_B;
        #pragma unroll
        for (int kk = 0; kk < 32; kk += 16) {
            uint32_t aF[4][4], bF[2][4][2];
            {
                int arow = warp_m * 64 + (lane & 15);
                int ak = kk + (lane >> 4) * 8;
                #pragma unroll
                for (int mt = 0; mt < 4; mt++)
                    ldsm4(aF[mt], base + ((arow + mt * 16) * LDSROW + ak) * 2);
            }
            {
                int brow = warp_n * 32 + (lane & 7) + (lane >> 4) * 8;
                int bk = kk + ((lane >> 3) & 1) * 8;
                #pragma unroll
                for (int hb = 0; hb < 2; hb++) {
                    uint32_t btile = (uint32_t)(1 + hb) * TILE_H * 2;
                    #pragma unroll
                    for (int g2 = 0; g2 < 2; g2++) {
                        uint32_t r[4];
                        ldsm4(r, base + btile + ((brow + g2 * 16) * LDSROW + bk) * 2);
                        bF[hb][g2 * 2][0] = r[0]; bF[hb][g2 * 2][1] = r[1];
                        bF[hb][g2 * 2 + 1][0] = r[2]; bF[hb][g2 * 2 + 1][1] = r[3];
                    }
                }
            }
            #pragma unroll
            for (int mt = 0; mt < 4; mt++)
                #pragma unroll
                for (int nt = 0; nt < 4; nt++) {
                    mma16816h(acc[mt][nt], aF[mt], bF[0][nt]);
                    mma16816h(acc[mt][nt], aF[mt], bF[1][nt]);
                }
        }
    }
    __syncthreads();   // compute done before epilogue may reuse dsm

    if (mode == 0) {
        #pragma unroll
        for (int mt = 0; mt < 4; mt++) {
            int m = m0 + warp_m * 64 + mt * 16 + (lane >> 2);
            #pragma unroll
            for (int nt = 0; nt < 4; nt++) {
                int n = n0 + warp_n * 32 + nt * 8 + (lane & 3) * 2;
                if (n < Nn) {
                    float2 v0 = make_float2(acc[mt][nt][0], acc[mt][nt][1]);
                    float2 v1 = make_float2(acc[mt][nt][2], acc[mt][nt][3]);
                    *(float2*)&C[(size_t)m * ldc + n] = v0;
                    *(float2*)&C[(size_t)(m + 8) * ldc + n] = v1;
                }
            }
        }
    } else {
        float* sT = (float*)dsm;   // [128 n][132 m]
        #pragma unroll
        for (int mt = 0; mt < 4; mt++) {
            int ml = warp_m * 64 + mt * 16 + (lane >> 2);
            #pragma unroll
            for (int nt = 0; nt < 4; nt++) {
                int nl = warp_n * 32 + nt * 8 + (lane & 3) * 2;
                sT[nl * 132 + ml]           = acc[mt][nt][0];
                sT[(nl + 1) * 132 + ml]     = acc[mt][nt][1];
                sT[nl * 132 + ml + 8]       = acc[mt][nt][2];
                sT[(nl + 1) * 132 + ml + 8] = acc[mt][nt][3];
            }
        }
        __syncthreads();
        int b = m0 >> 12;
        int l0 = m0 & (L_SEQ - 1);
        int n = tid >> 1;
        int part = (tid & 1) * 64;
        float* dst = C + ((size_t)b * DIMC + n0 + n) * L_SEQ + l0 + part;
        const float* src = sT + n * 132 + part;
        #pragma unroll
        for (int q = 0; q < 16; q++)
            *(float4*)(dst + q * 4) = *(const float4*)(src + q * 4);
    }
}

// ---------------- fp32 -> fp16 hi/lo split ----------------
__global__ __launch_bounds__(256) void cvt_kernel(const float* __restrict__ s,
                                                  __half* __restrict__ hi,
                                                  __half* __restrict__ lo, int n4) {
    int i = blockIdx.x * blockDim.x + threadIdx.x;
    if (i >= n4) return;
    float4 v = *(const float4*)(s + (size_t)i * 4);
    float vv[4] = {v.x, v.y, v.z, v.w};
    #pragma unroll
    for (int j = 0; j < 4; j++) {
        __half h = __float2half_rn(vv[j]);
        hi[(size_t)i * 4 + j] = h;
        lo[(size_t)i * 4 + j] = __float2half_rn(vv[j] - __half2float(h));
    }
}

__global__ __launch_bounds__(256) void cvt2_kernel(
    const float* __restrict__ s0, __half* __restrict__ hi0, __half* __restrict__ lo0, int n40,
    const float* __restrict__ s1, __half* __restrict__ hi1, __half* __restrict__ lo1, int n41) {
    int i = blockIdx.x * blockDim.x + threadIdx.x;
    const float* s; __half *hi, *lo;
    if (i < n40) { s = s0; hi = hi0; lo = lo0; }
    else { i -= n40; if (i >= n41) return; s = s1; hi = hi1; lo = lo1; }
    float4 v = *(const float4*)(s + (size_t)i * 4);
    float vv[4] = {v.x, v.y, v.z, v.w};
    #pragma unroll
    for (int j = 0; j < 4; j++) {
        __half h = __float2half_rn(vv[j]);
        hi[(size_t)i * 4 + j] = h;
        lo[(size_t)i * 4 + j] = __float2half_rn(vv[j] - __half2float(h));
    }
}

// ---------------- LayerNorm: x (B,C,L) -> xn (B*L, C) fp16 ----------------
__global__ __launch_bounds__(256) void ln_kernel(const float* __restrict__ x,
                                                 const float* __restrict__ w,
                                                 const float* __restrict__ bsh,
                                                 __half* __restrict__ xnh) {
    int b  = blockIdx.y;
    int l0 = blockIdx.x * 64;
    int tid = threadIdx.x;
    int ll = tid & 63;
    int cg = tid >> 6;

    __shared__ float ssum[4][64];
    __shared__ float ssq[4][64];
    __shared__ float smean[64];
    __shared__ float srstd[64];
    __shared__ float st[16][65];

    const float* xb = x + (size_t)b * DIMC * L_SEQ;

    float s = 0.f, sq = 0.f;
    for (int c = cg; c < DIMC; c += 4) {
        float v = xb[(size_t)c * L_SEQ + l0 + ll];
        s += v; sq += v * v;
    }
    ssum[cg][ll] = s; ssq[cg][ll] = sq;
    __syncthreads();
    if (tid < 64) {
        float S = ssum[0][tid] + ssum[1][tid] + ssum[2][tid] + ssum[3][tid];
        float Q = ssq[0][tid] + ssq[1][tid] + ssq[2][tid] + ssq[3][tid];
        float mu = S * (1.f / DIMC);
        float var = Q * (1.f / DIMC) - mu * mu;
        smean[tid] = mu;
        srstd[tid] = rsqrtf(var + 1e-5f);
    }
    __syncthreads();

    for (int c0 = 0; c0 < DIMC; c0 += 16) {
        #pragma unroll
        for (int r = 0; r < 4; r++) {
            int c = c0 + cg + r * 4;
            float v = xb[(size_t)c * L_SEQ + l0 + ll];
            st[cg + r * 4][ll] = (v - smean[ll]) * srstd[ll] * w[c] + bsh[c];
        }
        __syncthreads();
        int c2 = tid & 15, lr = tid >> 4;
        #pragma unroll
        for (int p = 0; p < 4; p++) {
            int l = lr + p * 16;
            xnh[((size_t)b * L_SEQ + l0 + l) * DIMC + c0 + c2] = __float2half_rn(st[c2][l]);
        }
        __syncthreads();
    }
}

// ---------------- fp32 tiled GEMM (dt only) ----------------
#define BM 128
#define BN 128
#define BKK 16
#define PAD 4

__global__ __launch_bounds__(256, 2) void gemm2_kernel(
    const float* __restrict__ A, int lda, int K,
    const float* __restrict__ W, int ldw, int N,
    float* __restrict__ C, int ldc, int mode,
    const float* __restrict__ bias) {

    __shared__ float As[2][BKK][BM + PAD];
    __shared__ float Bs[2][BKK][BN + PAD];

    int tid = threadIdx.x;
    int m0 = blockIdx.y * BM;
    int n0 = blockIdx.x * BN;
    int tm = tid & 15;
    int tn = tid >> 4;

    int lr = tid >> 2;
    int lk = (tid & 3) * 4;

    float4 pa[2], pb[2];
    int nt = (K + BKK - 1) / BKK;

    {
        int kk = lk;
        #pragma unroll
        for (int r = 0; r < 2; r++) {
            int m = lr + r * 64;
            float4 v = make_float4(0.f, 0.f, 0.f, 0.f);
            if (kk < K) v = *(const float4*)&A[(size_t)(m0 + m) * lda + kk];
            pa[r] = v;
            float4 u = make_float4(0.f, 0.f, 0.f, 0.f);
            if (kk < K && (n0 + m) < N) u = *(const float4*)&W[(size_t)(n0 + m) * ldw + kk];
            pb[r] = u;
        }
    }

    float acc[8][8];
    #pragma unroll
    for (int i = 0; i < 8; i++)
        #pragma unroll
        for (int j = 0; j < 8; j++) acc[i][j] = 0.f;

    for (int t = 0; t < nt; t++) {
        int buf = t & 1;
        #pragma unroll
        for (int r = 0; r < 2; r++) {
            int m = lr + r * 64;
            As[buf][lk + 0][m] = pa[r].x;
            As[buf][lk + 1][m] = pa[r].y;
            As[buf][lk + 2][m] = pa[r].z;
            As[buf][lk + 3][m] = pa[r].w;
            Bs[buf][lk + 0][m] = pb[r].x;
            Bs[buf][lk + 1][m] = pb[r].y;
            Bs[buf][lk + 2][m] = pb[r].z;
            Bs[buf][lk + 3][m] = pb[r].w;
        }
        __syncthreads();

        if (t + 1 < nt) {
            int kk = (t + 1) * BKK + lk;
            #pragma unroll
            for (int r = 0; r < 2; r++) {
                int m = lr + r * 64;
                float4 v = make_float4(0.f, 0.f, 0.f, 0.f);
                if (kk < K) v = *(const float4*)&A[(size_t)(m0 + m) * lda + kk];
                pa[r] = v;
                float4 u = make_float4(0.f, 0.f, 0.f, 0.f);
                if (kk < K && (n0 + m) < N) u = *(const float4*)&W[(size_t)(n0 + m) * ldw + kk];
                pb[r] = u;
            }
        }

        const float (*Ab)[BM + PAD] = As[buf];
        const float (*Bb)[BN + PAD] = Bs[buf];
        #pragma unroll
        for (int k = 0; k < BKK; k++) {
            float a[8], b[8];
            *(float4*)&a[0] = *(const float4*)&Ab[k][tm * 4];
            *(float4*)&a[4] = *(const float4*)&Ab[k][64 + tm * 4];
            *(float4*)&b[0] = *(const float4*)&Bb[k][tn * 4];
            *(float4*)&b[4] = *(const float4*)&Bb[k][64 + tn * 4];
            #pragma unroll
            for (int i = 0; i < 8; i++)
                #pragma unroll
                for (int j = 0; j < 8; j++)
                    acc[i][j] = fmaf(a[i], b[j], acc[i][j]);
        }
        __syncthreads();
    }

    #pragma unroll
    for (int ih = 0; ih < 2; ih++) {
        #pragma unroll
        for (int i4 = 0; i4 < 4; i4++) {
            int i = ih * 4 + i4;
            int m = m0 + ih * 64 + tm * 4 + i4;
            #pragma unroll
            for (int jh = 0; jh < 2; jh++) {
                int n = n0 + jh * 64 + tn * 4;
                if (n < N) {
                    float4 v = make_float4(acc[i][jh * 4 + 0], acc[i][jh * 4 + 1],
                                           acc[i][jh * 4 + 2], acc[i][jh * 4 + 3]);
                    if (mode == 1) {
                        float* vv = (float*)&v;
                        #pragma unroll
                        for (int j = 0; j < 4; j++) {
                            float z = vv[j] + bias[n + j];
                            vv[j] = fmaxf(z, 0.f) + log1pf(__expf(-fabsf(z)));
                        }
                    }
                    if (n + 3 < N) {
                        *(float4*)&C[(size_t)m * ldc + n] = v;
                    } else {
                        float* vv = (float*)&v;
                        #pragma unroll
                        for (int j = 0; j < 4; j++)
                            if (n + j < N) C[(size_t)m * ldc + n + j] = vv[j];
                    }
                }
            }
        }
    }
}

// ---------------- depthwise causal conv1d (k=4) + SiLU, smem-tiled ----------------
__global__ __launch_bounds__(256) void conv_silu2_kernel(const float* __restrict__ cw,
                                                         const float* __restrict__ cb,
                                                         const float* __restrict__ xz,
                                                         float* __restrict__ xc,
                                                         __half* __restrict__ xch) {
    __shared__ float sx[67][64];
    int d0 = blockIdx.x * 64;
    int mchunk = blockIdx.y;
    int l0 = (mchunk & 63) * 64;
    int b = mchunk >> 6;
    int tid = threadIdx.x;
    int tx = tid & 63, ty = tid >> 6;
    size_t rowbase = (size_t)b * L_SEQ;

    for (int r = ty; r < 67; r += 4) {
        int l = l0 - 3 + r;
        float v = 0.f;
        if (l >= 0) v = xz[(rowbase + l) * (2 * D_INNER) + d0 + tx];
        sx[r][tx] = v;
    }
    __syncthreads();

    int d = d0 + tx;
    float w0 = cw[d * 4 + 0], w1 = cw[d * 4 + 1];
    float w2 = cw[d * 4 + 2], w3 = cw[d * 4 + 3];
    float bias = cb[d];

    #pragma unroll 4
    for (int i = 0; i < 16; i++) {
        int ll = ty + i * 4;
        int r = ll + 3;
        float acc = bias;
        acc = fmaf(w3, sx[r][tx], acc);
        acc = fmaf(w2, sx[r - 1][tx], acc);
        acc = fmaf(w1, sx[r - 2][tx], acc);
        acc = fmaf(w0, sx[r - 3][tx], acc);
        float sg = 1.f / (1.f + __expf(-acc));
        float v = acc * sg;
        size_t o = (rowbase + l0 + ll) * D_INNER + d;
        xc[o] = v;
        xch[o] = __float2half_rn(v);
    }
}

// ---------------- selective scan v6: register-batched phases, 4-stage cp.async ----------------
// grid (32, 4), 384 threads. Per 16-step sub-chunk: parallel batch (loads + exp + f)
// into registers, then a pure-FFMA recurrence — caps latency exposure at the 4-cyc
// FFMA chain instead of per-step LDS/MUFU latency.
#define SCH6 32
#define CH6 24
#define NST6 4
#define NCH6 (L_SEQ / SCH6)     // 128
#define S6_BC 0
#define S6_D  4096
#define S6_X  7168
#define S6_Z  10240
#define S6_P  13312
#define S6_TOTAL (13312 + 32 * 24 * 20)   // 28672 floats = 114688 B

__global__ __launch_bounds__(384) void scan6_kernel(const float* __restrict__ A_log,
                                                    const float* __restrict__ Dp,
                                                    const float* __restrict__ dtv,
                                                    const float* __restrict__ xc,
                                                    const float* __restrict__ xdbl,
                                                    const float* __restrict__ xz,
                                                    __half* __restrict__ yh) {
    extern __shared__ float sm6[];
    float* sBC = sm6 + S6_BC;
    float* sD  = sm6 + S6_D;
    float* sX  = sm6 + S6_X;
    float* sZ  = sm6 + S6_Z;
    float* sP  = sm6 + S6_P;

    int b = blockIdx.y;
    int g = blockIdx.x;
    int d0 = g * CH6;
    int tid = threadIdx.x;
    size_t bL = (size_t)b * L_SEQ;

    int lane = tid & 31;
    int w = tid >> 5;
    int half = lane >> 4;
    int n = lane & 15;
    int dl = 2 * w + half;

    float An = -__expf(A_log[(d0 + dl) * D_STATE + n]);
    float h = 0.f;

    int rl = tid / CH6;
    int rc = tid % CH6;
    float Dd = Dp[d0 + rc];

    auto issue = [&](int c) {
        int l0 = c * SCH6;
        int buf = c % NST6;
        uint32_t bcs = smem_u32(sBC + buf * 1024);
        uint32_t ds  = smem_u32(sD  + buf * 768);
        uint32_t xs  = smem_u32(sX  + buf * 768);
        uint32_t zs  = smem_u32(sZ  + buf * 768);
        for (int u = tid; u < 832; u += 384) {
            if (u < 256) {
                int l = u >> 3, c4 = u & 7;
                cpasync16(bcs + (uint32_t)(l * 32 + c4 * 4) * 4,
                          xdbl + (bL + l0 + l) * XPN + DT_RANK + c4 * 4, 16);
            } else if (u < 448) {
                int v = u - 256; int l = v / 6, c4 = v % 6;
                cpasync16(ds + (uint32_t)(l * 24 + c4 * 4) * 4,
                          dtv + (bL + l0 + l) * D_INNER + d0 + c4 * 4, 16);
            } else if (u < 640) {
                int v = u - 448; int l = v / 6, c4 = v % 6;
                cpasync16(xs + (uint32_t)(l * 24 + c4 * 4) * 4,
                          xc + (bL + l0 + l) * D_INNER + d0 + c4 * 4, 16);
            } else {
                int v = u - 640; int l = v / 6, c4 = v % 6;
                cpasync16(zs + (uint32_t)(l * 24 + c4 * 4) * 4,
                          xz + (bL + l0 + l) * 2 * D_INNER + D_INNER + d0 + c4 * 4, 16);
            }
        }
        cp_commit();
    };

    issue(0);
    issue(1);

    for (int c = 0; c < NCH6; c++) {
        if (c + 2 < NCH6) { issue(c + 2); cp_wait<2>(); }
        else if (c + 1 < NCH6) { cp_wait<1>(); }
        else { cp_wait<0>(); }
        __syncthreads();                 // BAR_a

        int buf = c % NST6;
        const float* bD  = sD  + buf * 768;
        const float* bX  = sX  + buf * 768;
        const float* bBC = sBC + buf * 1024;

        // scan phase: two 16-step sub-chunks; batch (parallel) then recurrence (serial)
        #pragma unroll
        for (int s = 0; s < 2; s++) {
            float ev[16], fv[16], cv[16];
            #pragma unroll
            for (int j = 0; j < 16; j++) {
                int l = s * 16 + j;
                float dt = bD[l * 24 + dl];
                float xv = bX[l * 24 + dl];
                float Bn = bBC[l * 32 + n];
                cv[j] = bBC[l * 32 + 16 + n];
                ev[j] = __expf(dt * An);
                fv[j] = dt * xv * Bn;
            }
            #pragma unroll
            for (int j = 0; j < 16; j++) {
                h = fmaf(ev[j], h, fv[j]);
                sP[((s * 16 + j) * 24 + dl) * 20 + n] = h * cv[j];
            }
        }
        __syncthreads();                 // BAR_b

        #pragma unroll
        for (int i = 0; i < 2; i++) {
            int l = rl + i * 16;
            const float* p = sP + (l * 24 + rc) * 20;
            float4 a  = *(const float4*)p;
            float4 bq = *(const float4*)(p + 4);
            float4 cq = *(const float4*)(p + 8);
            float4 dq = *(const float4*)(p + 12);
            float s = ((a.x + a.y) + (a.z + a.w)) + ((bq.x + bq.y) + (bq.z + bq.w))
                    + ((cq.x + cq.y) + (cq.z + cq.w)) + ((dq.x + dq.y) + (dq.z + dq.w));
            float xv = bX[l * 24 + rc];
            float zv = sZ[buf * 768 + l * 24 + rc];
            float yv = fmaf(xv, Dd, s);
            yv *= zv / (1.f + __expf(-zv));
            size_t o = (bL + (size_t)c * SCH6 + l) * D_INNER + d0 + rc;
            yh[o] = __float2half_rn(yv);
        }
    }
}

// ---------------- launch ----------------
extern "C" void kernel_launch(void* const* d_in, const int* in_sizes, int n_in,
                              void* d_out, int out_size) {
    const float* x          = (const float*)d_in[0];
    const float* ln_w       = (const float*)d_in[1];
    const float* ln_b       = (const float*)d_in[2];
    const float* in_proj_w  = (const float*)d_in[3];
    const float* conv_w     = (const float*)d_in[4];
    const float* conv_b     = (const float*)d_in[5];
    const float* x_proj_w   = (const float*)d_in[6];
    const float* dt_w       = (const float*)d_in[7];
    const float* dt_b       = (const float*)d_in[8];
    const float* A_log      = (const float*)d_in[9];
    const float* Dp         = (const float*)d_in[10];
    const float* out_proj_w = (const float*)d_in[11];
    float* out = (float*)d_out;

    float *p_xz, *p_xc, *p_xdbl, *p_dtv;
    __half *p_xnh, *p_xch, *p_yh;
    __half *p_wih, *p_wil, *p_woh, *p_wol, *p_wxh, *p_wxl;
    cudaGetSymbolAddress((void**)&p_xz,   g_xz);
    cudaGetSymbolAddress((void**)&p_xc,   g_xc);
    cudaGetSymbolAddress((void**)&p_xdbl, g_xdbl);
    cudaGetSymbolAddress((void**)&p_dtv,  g_dtv);
    cudaGetSymbolAddress((void**)&p_xnh,  g_xn_h);
    cudaGetSymbolAddress((void**)&p_xch,  g_xc_h);
    cudaGetSymbolAddress((void**)&p_yh,   g_y_h);
    cudaGetSymbolAddress((void**)&p_wih,  g_wi_hi);
    cudaGetSymbolAddress((void**)&p_wil,  g_wi_lo);
    cudaGetSymbolAddress((void**)&p_woh,  g_wo_hi);
    cudaGetSymbolAddress((void**)&p_wol,  g_wo_lo);
    cudaGetSymbolAddress((void**)&p_wxh,  g_wx_hi);
    cudaGetSymbolAddress((void**)&p_wxl,  g_wx_lo);

    const int SC_SMEM = S6_TOTAL * 4;   // 114688 B
    cudaFuncSetAttribute(mmagemm_kernel, cudaFuncAttributeMaxDynamicSharedMemorySize, MM_SMEM);
    cudaFuncSetAttribute(scan6_kernel, cudaFuncAttributeMaxDynamicSharedMemorySize, SC_SMEM);

    // 0) weight hi/lo conversion
    int n4i = (2 * D_INNER * DIMC) / 4;
    cvt_kernel<<<(n4i + 255) / 256, 256>>>(in_proj_w, p_wih, p_wil, n4i);
    int n4o = (DIMC * D_INNER) / 4;
    int n4x = (XPN * D_INNER) / 4;
    cvt2_kernel<<<(n4o + n4x + 255) / 256, 256>>>(out_proj_w, p_woh, p_wol, n4o,
                                                  x_proj_w, p_wxh, p_wxl, n4x);

    // 1) LayerNorm -> xn fp16
    ln_kernel<<<dim3(L_SEQ / 64, B_SZ), 256>>>(x, ln_w, ln_b, p_xnh);

    // 2) in_proj (fp16 2-term) — profiled slot
    mmagemm_kernel<<<dim3(2 * D_INNER / 128, M_TOTAL / 128), 256, MM_SMEM>>>(
        p_xnh, p_wih, p_wil, DIMC, 2 * D_INNER, p_xz, 2 * D_INNER, 0);

    // 3) depthwise conv + silu -> xc fp32 + fp16
    conv_silu2_kernel<<<dim3(D_INNER / 64, M_TOTAL / 64), 256>>>(
        conv_w, conv_b, p_xz, p_xc, p_xch);

    // 4) x_proj (fp16 2-term, N=56 masked)
    mmagemm_kernel<<<dim3(1, M_TOTAL / 128), 256, MM_SMEM>>>(
        p_xch, p_wxh, p_wxl, D_INNER, XPN, p_xdbl, XPN, 0);

    // 5) dt + softplus (fp32 SIMT, K=24)
    gemm2_kernel<<<dim3(D_INNER / BN, M_TOTAL / BM), 256>>>(
        p_xdbl, XPN, DT_RANK, dt_w, DT_RANK, D_INNER, p_dtv, D_INNER, 1, dt_b);

    // 6) selective scan v6 -> y fp16
    scan6_kernel<<<dim3(D_INNER / CH6, B_SZ), 384, SC_SMEM>>>(
        A_log, Dp, p_dtv, p_xc, p_xdbl, p_xz, p_yh);

    // 7) out_proj (fp16 2-term, transposed store)
    mmagemm_kernel<<<dim3(DIMC / 128, M_TOTAL / 128), 256, MM_SMEM>>>(
        p_yh, p_woh, p_wol, D_INNER, DIMC, out, 0, 2);
}

// round 13
// speedup vs baseline: 1.4703x; 1.4703x over previous
#include <cuda_runtime.h>
#include <cuda_fp16.h>
#include <cstdint>

#define B_SZ 4
#define DIMC 384
#define L_SEQ 4096
#define D_INNER 768
#define D_STATE 16
#define DT_RANK 24
#define XPN 56
#define M_TOTAL (B_SZ * L_SEQ)      // 16384

// ---------------- scratch (no allocations allowed) ----------------
__device__ float g_xz[(size_t)M_TOTAL * 2 * D_INNER];
__device__ float g_xc[(size_t)M_TOTAL * D_INNER];
__device__ float g_xdbl[(size_t)M_TOTAL * XPN];
__device__ float g_dtv[(size_t)M_TOTAL * D_INNER];

__device__ __half g_xn_h[(size_t)M_TOTAL * DIMC];
__device__ __half g_xc_h[(size_t)M_TOTAL * D_INNER];
__device__ __half g_y_h[(size_t)M_TOTAL * D_INNER];
__device__ __half g_wi_hi[(size_t)2 * D_INNER * DIMC];
__device__ __half g_wi_lo[(size_t)2 * D_INNER * DIMC];
__device__ __half g_wo_hi[(size_t)DIMC * D_INNER];
__device__ __half g_wo_lo[(size_t)DIMC * D_INNER];
__device__ __half g_wx_hi[(size_t)XPN * D_INNER];
__device__ __half g_wx_lo[(size_t)XPN * D_INNER];

// ---------------- small PTX helpers (all base-target, sm_80+) ----------------
__device__ __forceinline__ uint32_t smem_u32(const void* p) {
    uint32_t a;
    asm("{ .reg .u64 t; cvta.to.shared.u64 t, %1; cvt.u32.u64 %0, t; }" : "=r"(a) : "l"(p));
    return a;
}
__device__ __forceinline__ void cpasync16(uint32_t sa, const void* g, int sz) {
    asm volatile("cp.async.cg.shared.global [%0], [%1], 16, %2;" :: "r"(sa), "l"(g), "r"(sz) : "memory");
}
__device__ __forceinline__ void cp_commit() {
    asm volatile("cp.async.commit_group;" ::: "memory");
}
template <int N> __device__ __forceinline__ void cp_wait() {
    asm volatile("cp.async.wait_group %0;" :: "n"(N) : "memory");
}
__device__ __forceinline__ void ldsm4(uint32_t* r, uint32_t addr) {
    asm volatile("ldmatrix.sync.aligned.m8n8.x4.shared.b16 {%0,%1,%2,%3}, [%4];"
                 : "=r"(r[0]), "=r"(r[1]), "=r"(r[2]), "=r"(r[3]) : "r"(addr));
}
__device__ __forceinline__ void mma16816h(float* d, const uint32_t* a, const uint32_t* b) {
    asm volatile(
        "mma.sync.aligned.m16n8k16.row.col.f32.f16.f16.f32 "
        "{%0,%1,%2,%3}, {%4,%5,%6,%7}, {%8,%9}, {%0,%1,%2,%3};"
        : "+f"(d[0]), "+f"(d[1]), "+f"(d[2]), "+f"(d[3])
        : "r"(a[0]), "r"(a[1]), "r"(a[2]), "r"(a[3]), "r"(b[0]), "r"(b[1]));
}

// ---------------- fp16 2-term mma.sync GEMM (256 thr, 2 CTA/SM, 3-stage ring) ----------------
// C[m,n] = sum_k A[m,k] * (Wh+Wl)[n,k]   (A truncated fp16; error = Al*W ~ 2^-12.8 rel)
// CTA tile 128x128, 8 warps (2m x 4n), warp tile 64x32, BK=32.
// Single barrier per chunk valid because NST >= depth+2 (see r9/r11 proof).
#define LDSROW 40
#define TILE_H (128 * LDSROW)       // 5120 halves
#define STAGE_B (3 * TILE_H * 2)    // 30720 B per stage
#define NST 3
#define MM_SMEM (NST * STAGE_B)     // 92160 B

__global__ __launch_bounds__(256, 2) void mmagemm_kernel(
    const __half* __restrict__ Ah,
    const __half* __restrict__ Bh, const __half* __restrict__ Bl,
    int K, int Nn, float* __restrict__ C, int ldc, int mode) {

    extern __shared__ __align__(16) uint8_t dsm[];
    uint32_t dsm_u = smem_u32(dsm);

    int tid = threadIdx.x;
    int wid = tid >> 5;
    int lane = tid & 31;
    int warp_m = wid & 1;      // 2 warps over m (2*64 = 128)
    int warp_n = wid >> 1;     // 4 warps over n (4*32 = 128)
    int m0 = blockIdx.y * 128;
    int n0 = blockIdx.x * 128;

    float acc[4][4][4];
    #pragma unroll
    for (int mt = 0; mt < 4; mt++)
        #pragma unroll
        for (int nt = 0; nt < 4; nt++)
            #pragma unroll
            for (int q = 0; q < 4; q++) acc[mt][nt][q] = 0.f;

    int nchunks = K >> 5;

    auto load_chunk = [&](int c) {
        int kc = c << 5;
        uint32_t sbase = dsm_u + (c % NST) * STAGE_B;
        #pragma unroll
        for (int i = 0; i < 6; i++) {
            int u = tid + i * 256;
            int tile = u >> 9;      // 0=A, 1=Bh, 2=Bl
            int v = u & 511;
            int row = v >> 2;
            int seg = v & 3;
            uint32_t sa = sbase + (tile * TILE_H + row * LDSROW + seg * 8) * 2;
            const __half* g;
            int sz = 16;
            if (tile == 0) {
                g = Ah + (size_t)(m0 + row) * K + kc + seg * 8;
            } else {
                int r = n0 + row;
                if (r >= Nn) { r = Nn - 1; sz = 0; }
                g = ((tile == 1) ? Bh : Bl) + (size_t)r * K + kc + seg * 8;
            }
            cpasync16(sa, g, sz);
        }
        cp_commit();
    };

    load_chunk(0);

    for (int c = 0; c < nchunks; c++) {
        if (c + 1 < nchunks) { load_chunk(c + 1); cp_wait<1>(); }
        else { cp_wait<0>(); }
        __syncthreads();   // single barrier per chunk

        uint32_t base = dsm_u + (c % NST) * STAGE_B;
        #pragma unroll
        for (int kk = 0; kk < 32; kk += 16) {
            uint32_t aF[4][4], bF[2][4][2];
            {
                int arow = warp_m * 64 + (lane & 15);
                int ak = kk + (lane >> 4) * 8;
                #pragma unroll
                for (int mt = 0; mt < 4; mt++)
                    ldsm4(aF[mt], base + ((arow + mt * 16) * LDSROW + ak) * 2);
            }
            {
                int brow = warp_n * 32 + (lane & 7) + (lane >> 4) * 8;
                int bk = kk + ((lane >> 3) & 1) * 8;
                #pragma unroll
                for (int hb = 0; hb < 2; hb++) {
                    uint32_t btile = (uint32_t)(1 + hb) * TILE_H * 2;
                    #pragma unroll
                    for (int g2 = 0; g2 < 2; g2++) {
                        uint32_t r[4];
                        ldsm4(r, base + btile + ((brow + g2 * 16) * LDSROW + bk) * 2);
                        bF[hb][g2 * 2][0] = r[0]; bF[hb][g2 * 2][1] = r[1];
                        bF[hb][g2 * 2 + 1][0] = r[2]; bF[hb][g2 * 2 + 1][1] = r[3];
                    }
                }
            }
            #pragma unroll
            for (int mt = 0; mt < 4; mt++)
                #pragma unroll
                for (int nt = 0; nt < 4; nt++) {
                    mma16816h(acc[mt][nt], aF[mt], bF[0][nt]);
                    mma16816h(acc[mt][nt], aF[mt], bF[1][nt]);
                }
        }
    }
    __syncthreads();   // compute done before epilogue may reuse dsm

    if (mode == 0) {
        #pragma unroll
        for (int mt = 0; mt < 4; mt++) {
            int m = m0 + warp_m * 64 + mt * 16 + (lane >> 2);
            #pragma unroll
            for (int nt = 0; nt < 4; nt++) {
                int n = n0 + warp_n * 32 + nt * 8 + (lane & 3) * 2;
                if (n < Nn) {
                    float2 v0 = make_float2(acc[mt][nt][0], acc[mt][nt][1]);
                    float2 v1 = make_float2(acc[mt][nt][2], acc[mt][nt][3]);
                    *(float2*)&C[(size_t)m * ldc + n] = v0;
                    *(float2*)&C[(size_t)(m + 8) * ldc + n] = v1;
                }
            }
        }
    } else {
        float* sT = (float*)dsm;   // [128 n][132 m]
        #pragma unroll
        for (int mt = 0; mt < 4; mt++) {
            int ml = warp_m * 64 + mt * 16 + (lane >> 2);
            #pragma unroll
            for (int nt = 0; nt < 4; nt++) {
                int nl = warp_n * 32 + nt * 8 + (lane & 3) * 2;
                sT[nl * 132 + ml]           = acc[mt][nt][0];
                sT[(nl + 1) * 132 + ml]     = acc[mt][nt][1];
                sT[nl * 132 + ml + 8]       = acc[mt][nt][2];
                sT[(nl + 1) * 132 + ml + 8] = acc[mt][nt][3];
            }
        }
        __syncthreads();
        int b = m0 >> 12;
        int l0 = m0 & (L_SEQ - 1);
        int n = tid >> 1;
        int part = (tid & 1) * 64;
        float* dst = C + ((size_t)b * DIMC + n0 + n) * L_SEQ + l0 + part;
        const float* src = sT + n * 132 + part;
        #pragma unroll
        for (int q = 0; q < 16; q++)
            *(float4*)(dst + q * 4) = *(const float4*)(src + q * 4);
    }
}

// ---------------- fp32 -> fp16 hi/lo split for all three weights, one launch ----------------
__global__ __launch_bounds__(256) void cvt3_kernel(
    const float* __restrict__ s0, __half* __restrict__ hi0, __half* __restrict__ lo0, int n40,
    const float* __restrict__ s1, __half* __restrict__ hi1, __half* __restrict__ lo1, int n41,
    const float* __restrict__ s2, __half* __restrict__ hi2, __half* __restrict__ lo2, int n42) {
    int i = blockIdx.x * blockDim.x + threadIdx.x;
    const float* s; __half *hi, *lo;
    if (i < n40) { s = s0; hi = hi0; lo = lo0; }
    else if (i < n40 + n41) { i -= n40; s = s1; hi = hi1; lo = lo1; }
    else { i -= n40 + n41; if (i >= n42) return; s = s2; hi = hi2; lo = lo2; }
    float4 v = *(const float4*)(s + (size_t)i * 4);
    float vv[4] = {v.x, v.y, v.z, v.w};
    #pragma unroll
    for (int j = 0; j < 4; j++) {
        __half h = __float2half_rn(vv[j]);
        hi[(size_t)i * 4 + j] = h;
        lo[(size_t)i * 4 + j] = __float2half_rn(vv[j] - __half2float(h));
    }
}

// ---------------- LayerNorm: x (B,C,L) -> xn (B*L, C) fp16 ----------------
__global__ __launch_bounds__(256) void ln_kernel(const float* __restrict__ x,
                                                 const float* __restrict__ w,
                                                 const float* __restrict__ bsh,
                                                 __half* __restrict__ xnh) {
    int b  = blockIdx.y;
    int l0 = blockIdx.x * 64;
    int tid = threadIdx.x;
    int ll = tid & 63;
    int cg = tid >> 6;

    __shared__ float ssum[4][64];
    __shared__ float ssq[4][64];
    __shared__ float smean[64];
    __shared__ float srstd[64];
    __shared__ float st[16][65];

    const float* xb = x + (size_t)b * DIMC * L_SEQ;

    float s = 0.f, sq = 0.f;
    for (int c = cg; c < DIMC; c += 4) {
        float v = xb[(size_t)c * L_SEQ + l0 + ll];
        s += v; sq += v * v;
    }
    ssum[cg][ll] = s; ssq[cg][ll] = sq;
    __syncthreads();
    if (tid < 64) {
        float S = ssum[0][tid] + ssum[1][tid] + ssum[2][tid] + ssum[3][tid];
        float Q = ssq[0][tid] + ssq[1][tid] + ssq[2][tid] + ssq[3][tid];
        float mu = S * (1.f / DIMC);
        float var = Q * (1.f / DIMC) - mu * mu;
        smean[tid] = mu;
        srstd[tid] = rsqrtf(var + 1e-5f);
    }
    __syncthreads();

    for (int c0 = 0; c0 < DIMC; c0 += 16) {
        #pragma unroll
        for (int r = 0; r < 4; r++) {
            int c = c0 + cg + r * 4;
            float v = xb[(size_t)c * L_SEQ + l0 + ll];
            st[cg + r * 4][ll] = (v - smean[ll]) * srstd[ll] * w[c] + bsh[c];
        }
        __syncthreads();
        int c2 = tid & 15, lr = tid >> 4;
        #pragma unroll
        for (int p = 0; p < 4; p++) {
            int l = lr + p * 16;
            xnh[((size_t)b * L_SEQ + l0 + l) * DIMC + c0 + c2] = __float2half_rn(st[c2][l]);
        }
        __syncthreads();
    }
}

// ---------------- fp32 tiled GEMM (dt only) ----------------
#define BM 128
#define BN 128
#define BKK 16
#define PAD 4

__global__ __launch_bounds__(256, 2) void gemm2_kernel(
    const float* __restrict__ A, int lda, int K,
    const float* __restrict__ W, int ldw, int N,
    float* __restrict__ C, int ldc, int mode,
    const float* __restrict__ bias) {

    __shared__ float As[2][BKK][BM + PAD];
    __shared__ float Bs[2][BKK][BN + PAD];

    int tid = threadIdx.x;
    int m0 = blockIdx.y * BM;
    int n0 = blockIdx.x * BN;
    int tm = tid & 15;
    int tn = tid >> 4;

    int lr = tid >> 2;
    int lk = (tid & 3) * 4;

    float4 pa[2], pb[2];
    int nt = (K + BKK - 1) / BKK;

    {
        int kk = lk;
        #pragma unroll
        for (int r = 0; r < 2; r++) {
            int m = lr + r * 64;
            float4 v = make_float4(0.f, 0.f, 0.f, 0.f);
            if (kk < K) v = *(const float4*)&A[(size_t)(m0 + m) * lda + kk];
            pa[r] = v;
            float4 u = make_float4(0.f, 0.f, 0.f, 0.f);
            if (kk < K && (n0 + m) < N) u = *(const float4*)&W[(size_t)(n0 + m) * ldw + kk];
            pb[r] = u;
        }
    }

    float acc[8][8];
    #pragma unroll
    for (int i = 0; i < 8; i++)
        #pragma unroll
        for (int j = 0; j < 8; j++) acc[i][j] = 0.f;

    for (int t = 0; t < nt; t++) {
        int buf = t & 1;
        #pragma unroll
        for (int r = 0; r < 2; r++) {
            int m = lr + r * 64;
            As[buf][lk + 0][m] = pa[r].x;
            As[buf][lk + 1][m] = pa[r].y;
            As[buf][lk + 2][m] = pa[r].z;
            As[buf][lk + 3][m] = pa[r].w;
            Bs[buf][lk + 0][m] = pb[r].x;
            Bs[buf][lk + 1][m] = pb[r].y;
            Bs[buf][lk + 2][m] = pb[r].z;
            Bs[buf][lk + 3][m] = pb[r].w;
        }
        __syncthreads();

        if (t + 1 < nt) {
            int kk = (t + 1) * BKK + lk;
            #pragma unroll
            for (int r = 0; r < 2; r++) {
                int m = lr + r * 64;
                float4 v = make_float4(0.f, 0.f, 0.f, 0.f);
                if (kk < K) v = *(const float4*)&A[(size_t)(m0 + m) * lda + kk];
                pa[r] = v;
                float4 u = make_float4(0.f, 0.f, 0.f, 0.f);
                if (kk < K && (n0 + m) < N) u = *(const float4*)&W[(size_t)(n0 + m) * ldw + kk];
                pb[r] = u;
            }
        }

        const float (*Ab)[BM + PAD] = As[buf];
        const float (*Bb)[BN + PAD] = Bs[buf];
        #pragma unroll
        for (int k = 0; k < BKK; k++) {
            float a[8], b[8];
            *(float4*)&a[0] = *(const float4*)&Ab[k][tm * 4];
            *(float4*)&a[4] = *(const float4*)&Ab[k][64 + tm * 4];
            *(float4*)&b[0] = *(const float4*)&Bb[k][tn * 4];
            *(float4*)&b[4] = *(const float4*)&Bb[k][64 + tn * 4];
            #pragma unroll
            for (int i = 0; i < 8; i++)
                #pragma unroll
                for (int j = 0; j < 8; j++)
                    acc[i][j] = fmaf(a[i], b[j], acc[i][j]);
        }
        __syncthreads();
    }

    #pragma unroll
    for (int ih = 0; ih < 2; ih++) {
        #pragma unroll
        for (int i4 = 0; i4 < 4; i4++) {
            int i = ih * 4 + i4;
            int m = m0 + ih * 64 + tm * 4 + i4;
            #pragma unroll
            for (int jh = 0; jh < 2; jh++) {
                int n = n0 + jh * 64 + tn * 4;
                if (n < N) {
                    float4 v = make_float4(acc[i][jh * 4 + 0], acc[i][jh * 4 + 1],
                                           acc[i][jh * 4 + 2], acc[i][jh * 4 + 3]);
                    if (mode == 1) {
                        float* vv = (float*)&v;
                        #pragma unroll
                        for (int j = 0; j < 4; j++) {
                            float z = vv[j] + bias[n + j];
                            vv[j] = fmaxf(z, 0.f) + log1pf(__expf(-fabsf(z)));
                        }
                    }
                    if (n + 3 < N) {
                        *(float4*)&C[(size_t)m * ldc + n] = v;
                    } else {
                        float* vv = (float*)&v;
                        #pragma unroll
                        for (int j = 0; j < 4; j++)
                            if (n + j < N) C[(size_t)m * ldc + n + j] = vv[j];
                    }
                }
            }
        }
    }
}

// ---------------- depthwise causal conv1d (k=4) + SiLU, smem-tiled ----------------
__global__ __launch_bounds__(256) void conv_silu2_kernel(const float* __restrict__ cw,
                                                         const float* __restrict__ cb,
                                                         const float* __restrict__ xz,
                                                         float* __restrict__ xc,
                                                         __half* __restrict__ xch) {
    __shared__ float sx[67][64];
    int d0 = blockIdx.x * 64;
    int mchunk = blockIdx.y;
    int l0 = (mchunk & 63) * 64;
    int b = mchunk >> 6;
    int tid = threadIdx.x;
    int tx = tid & 63, ty = tid >> 6;
    size_t rowbase = (size_t)b * L_SEQ;

    for (int r = ty; r < 67; r += 4) {
        int l = l0 - 3 + r;
        float v = 0.f;
        if (l >= 0) v = xz[(rowbase + l) * (2 * D_INNER) + d0 + tx];
        sx[r][tx] = v;
    }
    __syncthreads();

    int d = d0 + tx;
    float w0 = cw[d * 4 + 0], w1 = cw[d * 4 + 1];
    float w2 = cw[d * 4 + 2], w3 = cw[d * 4 + 3];
    float bias = cb[d];

    #pragma unroll 4
    for (int i = 0; i < 16; i++) {
        int ll = ty + i * 4;
        int r = ll + 3;
        float acc = bias;
        acc = fmaf(w3, sx[r][tx], acc);
        acc = fmaf(w2, sx[r - 1][tx], acc);
        acc = fmaf(w1, sx[r - 2][tx], acc);
        acc = fmaf(w0, sx[r - 3][tx], acc);
        float sg = 1.f / (1.f + __expf(-acc));
        float v = acc * sg;
        size_t o = (rowbase + l0 + ll) * D_INNER + d;
        xc[o] = v;
        xch[o] = __float2half_rn(v);
    }
}

// ---------------- selective scan v5: phase-split, 4-stage cp.async, SCH=32 ----------------
#define SCH5 32
#define CH5 24
#define NST5 4
#define NCH5 (L_SEQ / SCH5)     // 128
#define S5_BC 0
#define S5_D  4096
#define S5_X  7168
#define S5_Z  10240
#define S5_P  13312
#define S5_TOTAL (13312 + 32 * 24 * 20)   // 28672 floats = 114688 B

__global__ __launch_bounds__(384) void scan5_kernel(const float* __restrict__ A_log,
                                                    const float* __restrict__ Dp,
                                                    const float* __restrict__ dtv,
                                                    const float* __restrict__ xc,
                                                    const float* __restrict__ xdbl,
                                                    const float* __restrict__ xz,
                                                    __half* __restrict__ yh) {
    extern __shared__ float sm5[];
    float* sBC = sm5 + S5_BC;
    float* sD  = sm5 + S5_D;
    float* sX  = sm5 + S5_X;
    float* sZ  = sm5 + S5_Z;
    float* sP  = sm5 + S5_P;

    int b = blockIdx.y;
    int g = blockIdx.x;
    int d0 = g * CH5;
    int tid = threadIdx.x;
    size_t bL = (size_t)b * L_SEQ;

    int lane = tid & 31;
    int w = tid >> 5;
    int half = lane >> 4;
    int n = lane & 15;
    int dl = 2 * w + half;

    float An = -__expf(A_log[(d0 + dl) * D_STATE + n]);
    float h = 0.f;

    int rl = tid / CH5;
    int rc = tid % CH5;
    float Dd = Dp[d0 + rc];

    auto issue = [&](int c) {
        int l0 = c * SCH5;
        int buf = c % NST5;
        uint32_t bcs = smem_u32(sBC + buf * 1024);
        uint32_t ds  = smem_u32(sD  + buf * 768);
        uint32_t xs  = smem_u32(sX  + buf * 768);
        uint32_t zs  = smem_u32(sZ  + buf * 768);
        for (int u = tid; u < 832; u += 384) {
            if (u < 256) {
                int l = u >> 3, c4 = u & 7;
                cpasync16(bcs + (uint32_t)(l * 32 + c4 * 4) * 4,
                          xdbl + (bL + l0 + l) * XPN + DT_RANK + c4 * 4, 16);
            } else if (u < 448) {
                int v = u - 256; int l = v / 6, c4 = v % 6;
                cpasync16(ds + (uint32_t)(l * 24 + c4 * 4) * 4,
                          dtv + (bL + l0 + l) * D_INNER + d0 + c4 * 4, 16);
            } else if (u < 640) {
                int v = u - 448; int l = v / 6, c4 = v % 6;
                cpasync16(xs + (uint32_t)(l * 24 + c4 * 4) * 4,
                          xc + (bL + l0 + l) * D_INNER + d0 + c4 * 4, 16);
            } else {
                int v = u - 640; int l = v / 6, c4 = v % 6;
                cpasync16(zs + (uint32_t)(l * 24 + c4 * 4) * 4,
                          xz + (bL + l0 + l) * 2 * D_INNER + D_INNER + d0 + c4 * 4, 16);
            }
        }
        cp_commit();
    };

    issue(0);
    issue(1);

    for (int c = 0; c < NCH5; c++) {
        if (c + 2 < NCH5) { issue(c + 2); cp_wait<2>(); }
        else if (c + 1 < NCH5) { cp_wait<1>(); }
        else { cp_wait<0>(); }
        __syncthreads();                 // BAR_a

        int buf = c % NST5;
        const float* bD  = sD  + buf * 768;
        const float* bX  = sX  + buf * 768;
        const float* bBC = sBC + buf * 1024;

        #pragma unroll 8
        for (int l = 0; l < SCH5; l++) {
            float dt = bD[l * 24 + dl];
            float xv = bX[l * 24 + dl];
            float Bn = bBC[l * 32 + n];
            float Cn = bBC[l * 32 + 16 + n];
            float e = __expf(dt * An);
            h = fmaf(e, h, dt * xv * Bn);
            sP[(l * 24 + dl) * 20 + n] = h * Cn;
        }
        __syncthreads();                 // BAR_b

        #pragma unroll
        for (int i = 0; i < 2; i++) {
            int l = rl + i * 16;
            const float* p = sP + (l * 24 + rc) * 20;
            float4 a  = *(const float4*)p;
            float4 bq = *(const float4*)(p + 4);
            float4 cq = *(const float4*)(p + 8);
            float4 dq = *(const float4*)(p + 12);
            float s = ((a.x + a.y) + (a.z + a.w)) + ((bq.x + bq.y) + (bq.z + bq.w))
                    + ((cq.x + cq.y) + (cq.z + cq.w)) + ((dq.x + dq.y) + (dq.z + dq.w));
            float xv = bX[l * 24 + rc];
            float zv = sZ[buf * 768 + l * 24 + rc];
            float yv = fmaf(xv, Dd, s);
            yv *= zv / (1.f + __expf(-zv));
            size_t o = (bL + (size_t)c * SCH5 + l) * D_INNER + d0 + rc;
            yh[o] = __float2half_rn(yv);
        }
    }
}

// ---------------- launch ----------------
extern "C" void kernel_launch(void* const* d_in, const int* in_sizes, int n_in,
                              void* d_out, int out_size) {
    const float* x          = (const float*)d_in[0];
    const float* ln_w       = (const float*)d_in[1];
    const float* ln_b       = (const float*)d_in[2];
    const float* in_proj_w  = (const float*)d_in[3];
    const float* conv_w     = (const float*)d_in[4];
    const float* conv_b     = (const float*)d_in[5];
    const float* x_proj_w   = (const float*)d_in[6];
    const float* dt_w       = (const float*)d_in[7];
    const float* dt_b       = (const float*)d_in[8];
    const float* A_log      = (const float*)d_in[9];
    const float* Dp         = (const float*)d_in[10];
    const float* out_proj_w = (const float*)d_in[11];
    float* out = (float*)d_out;

    float *p_xz, *p_xc, *p_xdbl, *p_dtv;
    __half *p_xnh, *p_xch, *p_yh;
    __half *p_wih, *p_wil, *p_woh, *p_wol, *p_wxh, *p_wxl;
    cudaGetSymbolAddress((void**)&p_xz,   g_xz);
    cudaGetSymbolAddress((void**)&p_xc,   g_xc);
    cudaGetSymbolAddress((void**)&p_xdbl, g_xdbl);
    cudaGetSymbolAddress((void**)&p_dtv,  g_dtv);
    cudaGetSymbolAddress((void**)&p_xnh,  g_xn_h);
    cudaGetSymbolAddress((void**)&p_xch,  g_xc_h);
    cudaGetSymbolAddress((void**)&p_yh,   g_y_h);
    cudaGetSymbolAddress((void**)&p_wih,  g_wi_hi);
    cudaGetSymbolAddress((void**)&p_wil,  g_wi_lo);
    cudaGetSymbolAddress((void**)&p_woh,  g_wo_hi);
    cudaGetSymbolAddress((void**)&p_wol,  g_wo_lo);
    cudaGetSymbolAddress((void**)&p_wxh,  g_wx_hi);
    cudaGetSymbolAddress((void**)&p_wxl,  g_wx_lo);

    const int SC_SMEM = S5_TOTAL * 4;   // 114688 B
    cudaFuncSetAttribute(mmagemm_kernel, cudaFuncAttributeMaxDynamicSharedMemorySize, MM_SMEM);
    cudaFuncSetAttribute(scan5_kernel, cudaFuncAttributeMaxDynamicSharedMemorySize, SC_SMEM);

    // 0) weight hi/lo conversion (single launch)
    int n4i = (2 * D_INNER * DIMC) / 4;
    int n4o = (DIMC * D_INNER) / 4;
    int n4x = (XPN * D_INNER) / 4;
    cvt3_kernel<<<(n4i + n4o + n4x + 255) / 256, 256>>>(
        in_proj_w, p_wih, p_wil, n4i,
        out_proj_w, p_woh, p_wol, n4o,
        x_proj_w, p_wxh, p_wxl, n4x);

    // 1) LayerNorm -> xn fp16
    ln_kernel<<<dim3(L_SEQ / 64, B_SZ), 256>>>(x, ln_w, ln_b, p_xnh);

    // 2) in_proj (fp16 2-term) — profiled slot
    mmagemm_kernel<<<dim3(2 * D_INNER / 128, M_TOTAL / 128), 256, MM_SMEM>>>(
        p_xnh, p_wih, p_wil, DIMC, 2 * D_INNER, p_xz, 2 * D_INNER, 0);

    // 3) depthwise conv + silu -> xc fp32 + fp16
    conv_silu2_kernel<<<dim3(D_INNER / 64, M_TOTAL / 64), 256>>>(
        conv_w, conv_b, p_xz, p_xc, p_xch);

    // 4) x_proj (fp16 2-term, N=56 masked)
    mmagemm_kernel<<<dim3(1, M_TOTAL / 128), 256, MM_SMEM>>>(
        p_xch, p_wxh, p_wxl, D_INNER, XPN, p_xdbl, XPN, 0);

    // 5) dt + softplus (fp32 SIMT, K=24)
    gemm2_kernel<<<dim3(D_INNER / BN, M_TOTAL / BM), 256>>>(
        p_xdbl, XPN, DT_RANK, dt_w, DT_RANK, D_INNER, p_dtv, D_INNER, 1, dt_b);

    // 6) selective scan v5 -> y fp16
    scan5_kernel<<<dim3(D_INNER / CH5, B_SZ), 384, SC_SMEM>>>(
        A_log, Dp, p_dtv, p_xc, p_xdbl, p_xz, p_yh);

    // 7) out_proj (fp16 2-term, transposed store)
    mmagemm_kernel<<<dim3(DIMC / 128, M_TOTAL / 128), 256, MM_SMEM>>>(
        p_yh, p_woh, p_wol, D_INNER, DIMC, out, 0, 2);
}

// round 14
// speedup vs baseline: 1.5722x; 1.0693x over previous
#include <cuda_runtime.h>
#include <cuda_fp16.h>
#include <cstdint>

#define B_SZ 4
#define DIMC 384
#define L_SEQ 4096
#define D_INNER 768
#define D_STATE 16
#define DT_RANK 24
#define XPN 56
#define M_TOTAL (B_SZ * L_SEQ)      // 16384

// ---------------- scratch (no allocations allowed) ----------------
__device__ float g_xz[(size_t)M_TOTAL * 2 * D_INNER];
__device__ float g_xc[(size_t)M_TOTAL * D_INNER];
__device__ float g_xdbl[(size_t)M_TOTAL * XPN];
__device__ float g_dtv[(size_t)M_TOTAL * D_INNER];

__device__ __half g_xn_h[(size_t)M_TOTAL * DIMC];
__device__ __half g_xc_h[(size_t)M_TOTAL * D_INNER];
__device__ __half g_y_h[(size_t)M_TOTAL * D_INNER];
__device__ __half g_wi_hi[(size_t)2 * D_INNER * DIMC];
__device__ __half g_wi_lo[(size_t)2 * D_INNER * DIMC];
__device__ __half g_wo_hi[(size_t)DIMC * D_INNER];
__device__ __half g_wo_lo[(size_t)DIMC * D_INNER];
__device__ __half g_wx_hi[(size_t)XPN * D_INNER];
__device__ __half g_wx_lo[(size_t)XPN * D_INNER];

// ---------------- small PTX helpers (all base-target, sm_80+) ----------------
__device__ __forceinline__ uint32_t smem_u32(const void* p) {
    uint32_t a;
    asm("{ .reg .u64 t; cvta.to.shared.u64 t, %1; cvt.u32.u64 %0, t; }" : "=r"(a) : "l"(p));
    return a;
}
__device__ __forceinline__ void cpasync16(uint32_t sa, const void* g, int sz) {
    asm volatile("cp.async.cg.shared.global [%0], [%1], 16, %2;" :: "r"(sa), "l"(g), "r"(sz) : "memory");
}
__device__ __forceinline__ void cp_commit() {
    asm volatile("cp.async.commit_group;" ::: "memory");
}
template <int N> __device__ __forceinline__ void cp_wait() {
    asm volatile("cp.async.wait_group %0;" :: "n"(N) : "memory");
}
__device__ __forceinline__ void ldsm4(uint32_t* r, uint32_t addr) {
    asm volatile("ldmatrix.sync.aligned.m8n8.x4.shared.b16 {%0,%1,%2,%3}, [%4];"
                 : "=r"(r[0]), "=r"(r[1]), "=r"(r[2]), "=r"(r[3]) : "r"(addr));
}
__device__ __forceinline__ void mma16816h(float* d, const uint32_t* a, const uint32_t* b) {
    asm volatile(
        "mma.sync.aligned.m16n8k16.row.col.f32.f16.f16.f32 "
        "{%0,%1,%2,%3}, {%4,%5,%6,%7}, {%8,%9}, {%0,%1,%2,%3};"
        : "+f"(d[0]), "+f"(d[1]), "+f"(d[2]), "+f"(d[3])
        : "r"(a[0]), "r"(a[1]), "r"(a[2]), "r"(a[3]), "r"(b[0]), "r"(b[1]));
}

// ---------------- fp16 2-term mma.sync GEMM (256 thr, 2 CTA/SM, 3-stage ring) ----------------
#define LDSROW 40
#define TILE_H (128 * LDSROW)       // 5120 halves
#define STAGE_B (3 * TILE_H * 2)    // 30720 B per stage
#define NST 3
#define MM_SMEM (NST * STAGE_B)     // 92160 B

__global__ __launch_bounds__(256, 2) void mmagemm_kernel(
    const __half* __restrict__ Ah,
    const __half* __restrict__ Bh, const __half* __restrict__ Bl,
    int K, int Nn, float* __restrict__ C, int ldc, int mode) {

    extern __shared__ __align__(16) uint8_t dsm[];
    uint32_t dsm_u = smem_u32(dsm);

    int tid = threadIdx.x;
    int wid = tid >> 5;
    int lane = tid & 31;
    int warp_m = wid & 1;
    int warp_n = wid >> 1;
    int m0 = blockIdx.y * 128;
    int n0 = blockIdx.x * 128;

    float acc[4][4][4];
    #pragma unroll
    for (int mt = 0; mt < 4; mt++)
        #pragma unroll
        for (int nt = 0; nt < 4; nt++)
            #pragma unroll
            for (int q = 0; q < 4; q++) acc[mt][nt][q] = 0.f;

    int nchunks = K >> 5;

    auto load_chunk = [&](int c) {
        int kc = c << 5;
        uint32_t sbase = dsm_u + (c % NST) * STAGE_B;
        #pragma unroll
        for (int i = 0; i < 6; i++) {
            int u = tid + i * 256;
            int tile = u >> 9;
            int v = u & 511;
            int row = v >> 2;
            int seg = v & 3;
            uint32_t sa = sbase + (tile * TILE_H + row * LDSROW + seg * 8) * 2;
            const __half* g;
            int sz = 16;
            if (tile == 0) {
                g = Ah + (size_t)(m0 + row) * K + kc + seg * 8;
            } else {
                int r = n0 + row;
                if (r >= Nn) { r = Nn - 1; sz = 0; }
                g = ((tile == 1) ? Bh : Bl) + (size_t)r * K + kc + seg * 8;
            }
            cpasync16(sa, g, sz);
        }
        cp_commit();
    };

    load_chunk(0);

    for (int c = 0; c < nchunks; c++) {
        if (c + 1 < nchunks) { load_chunk(c + 1); cp_wait<1>(); }
        else { cp_wait<0>(); }
        __syncthreads();

        uint32_t base = dsm_u + (c % NST) * STAGE_B;
        #pragma unroll
        for (int kk = 0; kk < 32; kk += 16) {
            uint32_t aF[4][4], bF[2][4][2];
            {
                int arow = warp_m * 64 + (lane & 15);
                int ak = kk + (lane >> 4) * 8;
                #pragma unroll
                for (int mt = 0; mt < 4; mt++)
                    ldsm4(aF[mt], base + ((arow + mt * 16) * LDSROW + ak) * 2);
            }
            {
                int brow = warp_n * 32 + (lane & 7) + (lane >> 4) * 8;
                int bk = kk + ((lane >> 3) & 1) * 8;
                #pragma unroll
                for (int hb = 0; hb < 2; hb++) {
                    uint32_t btile = (uint32_t)(1 + hb) * TILE_H * 2;
                    #pragma unroll
                    for (int g2 = 0; g2 < 2; g2++) {
                        uint32_t r[4];
                        ldsm4(r, base + btile + ((brow + g2 * 16) * LDSROW + bk) * 2);
                        bF[hb][g2 * 2][0] = r[0]; bF[hb][g2 * 2][1] = r[1];
                        bF[hb][g2 * 2 + 1][0] = r[2]; bF[hb][g2 * 2 + 1][1] = r[3];
                    }
                }
            }
            #pragma unroll
            for (int mt = 0; mt < 4; mt++)
                #pragma unroll
                for (int nt = 0; nt < 4; nt++) {
                    mma16816h(acc[mt][nt], aF[mt], bF[0][nt]);
                    mma16816h(acc[mt][nt], aF[mt], bF[1][nt]);
                }
        }
    }
    __syncthreads();

    if (mode == 0) {
        #pragma unroll
        for (int mt = 0; mt < 4; mt++) {
            int m = m0 + warp_m * 64 + mt * 16 + (lane >> 2);
            #pragma unroll
            for (int nt = 0; nt < 4; nt++) {
                int n = n0 + warp_n * 32 + nt * 8 + (lane & 3) * 2;
                if (n < Nn) {
                    float2 v0 = make_float2(acc[mt][nt][0], acc[mt][nt][1]);
                    float2 v1 = make_float2(acc[mt][nt][2], acc[mt][nt][3]);
                    *(float2*)&C[(size_t)m * ldc + n] = v0;
                    *(float2*)&C[(size_t)(m + 8) * ldc + n] = v1;
                }
            }
        }
    } else {
        float* sT = (float*)dsm;   // [128 n][132 m]
        #pragma unroll
        for (int mt = 0; mt < 4; mt++) {
            int ml = warp_m * 64 + mt * 16 + (lane >> 2);
            #pragma unroll
            for (int nt = 0; nt < 4; nt++) {
                int nl = warp_n * 32 + nt * 8 + (lane & 3) * 2;
                sT[nl * 132 + ml]           = acc[mt][nt][0];
                sT[(nl + 1) * 132 + ml]     = acc[mt][nt][1];
                sT[nl * 132 + ml + 8]       = acc[mt][nt][2];
                sT[(nl + 1) * 132 + ml + 8] = acc[mt][nt][3];
            }
        }
        __syncthreads();
        int b = m0 >> 12;
        int l0 = m0 & (L_SEQ - 1);
        int n = tid >> 1;
        int part = (tid & 1) * 64;
        float* dst = C + ((size_t)b * DIMC + n0 + n) * L_SEQ + l0 + part;
        const float* src = sT + n * 132 + part;
        #pragma unroll
        for (int q = 0; q < 16; q++)
            *(float4*)(dst + q * 4) = *(const float4*)(src + q * 4);
    }
}

// ---------------- fp32 -> fp16 hi/lo split for all three weights, one launch ----------------
__global__ __launch_bounds__(256) void cvt3_kernel(
    const float* __restrict__ s0, __half* __restrict__ hi0, __half* __restrict__ lo0, int n40,
    const float* __restrict__ s1, __half* __restrict__ hi1, __half* __restrict__ lo1, int n41,
    const float* __restrict__ s2, __half* __restrict__ hi2, __half* __restrict__ lo2, int n42) {
    int i = blockIdx.x * blockDim.x + threadIdx.x;
    const float* s; __half *hi, *lo;
    if (i < n40) { s = s0; hi = hi0; lo = lo0; }
    else if (i < n40 + n41) { i -= n40; s = s1; hi = hi1; lo = lo1; }
    else { i -= n40 + n41; if (i >= n42) return; s = s2; hi = hi2; lo = lo2; }
    float4 v = *(const float4*)(s + (size_t)i * 4);
    float vv[4] = {v.x, v.y, v.z, v.w};
    #pragma unroll
    for (int j = 0; j < 4; j++) {
        __half h = __float2half_rn(vv[j]);
        hi[(size_t)i * 4 + j] = h;
        lo[(size_t)i * 4 + j] = __float2half_rn(vv[j] - __half2float(h));
    }
}

// ---------------- LayerNorm: x (B,C,L) -> xn (B*L, C) fp16 ----------------
__global__ __launch_bounds__(256) void ln_kernel(const float* __restrict__ x,
                                                 const float* __restrict__ w,
                                                 const float* __restrict__ bsh,
                                                 __half* __restrict__ xnh) {
    int b  = blockIdx.y;
    int l0 = blockIdx.x * 64;
    int tid = threadIdx.x;
    int ll = tid & 63;
    int cg = tid >> 6;

    __shared__ float ssum[4][64];
    __shared__ float ssq[4][64];
    __shared__ float smean[64];
    __shared__ float srstd[64];
    __shared__ float st[16][65];

    const float* xb = x + (size_t)b * DIMC * L_SEQ;

    float s = 0.f, sq = 0.f;
    for (int c = cg; c < DIMC; c += 4) {
        float v = xb[(size_t)c * L_SEQ + l0 + ll];
        s += v; sq += v * v;
    }
    ssum[cg][ll] = s; ssq[cg][ll] = sq;
    __syncthreads();
    if (tid < 64) {
        float S = ssum[0][tid] + ssum[1][tid] + ssum[2][tid] + ssum[3][tid];
        float Q = ssq[0][tid] + ssq[1][tid] + ssq[2][tid] + ssq[3][tid];
        float mu = S * (1.f / DIMC);
        float var = Q * (1.f / DIMC) - mu * mu;
        smean[tid] = mu;
        srstd[tid] = rsqrtf(var + 1e-5f);
    }
    __syncthreads();

    for (int c0 = 0; c0 < DIMC; c0 += 16) {
        #pragma unroll
        for (int r = 0; r < 4; r++) {
            int c = c0 + cg + r * 4;
            float v = xb[(size_t)c * L_SEQ + l0 + ll];
            st[cg + r * 4][ll] = (v - smean[ll]) * srstd[ll] * w[c] + bsh[c];
        }
        __syncthreads();
        int c2 = tid & 15, lr = tid >> 4;
        #pragma unroll
        for (int p = 0; p < 4; p++) {
            int l = lr + p * 16;
            xnh[((size_t)b * L_SEQ + l0 + l) * DIMC + c0 + c2] = __float2half_rn(st[c2][l]);
        }
        __syncthreads();
    }
}

// ---------------- fp32 tiled GEMM (dt only) ----------------
#define BM 128
#define BN 128
#define BKK 16
#define PAD 4

__global__ __launch_bounds__(256, 2) void gemm2_kernel(
    const float* __restrict__ A, int lda, int K,
    const float* __restrict__ W, int ldw, int N,
    float* __restrict__ C, int ldc, int mode,
    const float* __restrict__ bias) {

    __shared__ float As[2][BKK][BM + PAD];
    __shared__ float Bs[2][BKK][BN + PAD];

    int tid = threadIdx.x;
    int m0 = blockIdx.y * BM;
    int n0 = blockIdx.x * BN;
    int tm = tid & 15;
    int tn = tid >> 4;

    int lr = tid >> 2;
    int lk = (tid & 3) * 4;

    float4 pa[2], pb[2];
    int nt = (K + BKK - 1) / BKK;

    {
        int kk = lk;
        #pragma unroll
        for (int r = 0; r < 2; r++) {
            int m = lr + r * 64;
            float4 v = make_float4(0.f, 0.f, 0.f, 0.f);
            if (kk < K) v = *(const float4*)&A[(size_t)(m0 + m) * lda + kk];
            pa[r] = v;
            float4 u = make_float4(0.f, 0.f, 0.f, 0.f);
            if (kk < K && (n0 + m) < N) u = *(const float4*)&W[(size_t)(n0 + m) * ldw + kk];
            pb[r] = u;
        }
    }

    float acc[8][8];
    #pragma unroll
    for (int i = 0; i < 8; i++)
        #pragma unroll
        for (int j = 0; j < 8; j++) acc[i][j] = 0.f;

    for (int t = 0; t < nt; t++) {
        int buf = t & 1;
        #pragma unroll
        for (int r = 0; r < 2; r++) {
            int m = lr + r * 64;
            As[buf][lk + 0][m] = pa[r].x;
            As[buf][lk + 1][m] = pa[r].y;
            As[buf][lk + 2][m] = pa[r].z;
            As[buf][lk + 3][m] = pa[r].w;
            Bs[buf][lk + 0][m] = pb[r].x;
            Bs[buf][lk + 1][m] = pb[r].y;
            Bs[buf][lk + 2][m] = pb[r].z;
            Bs[buf][lk + 3][m] = pb[r].w;
        }
        __syncthreads();

        if (t + 1 < nt) {
            int kk = (t + 1) * BKK + lk;
            #pragma unroll
            for (int r = 0; r < 2; r++) {
                int m = lr + r * 64;
                float4 v = make_float4(0.f, 0.f, 0.f, 0.f);
                if (kk < K) v = *(const float4*)&A[(size_t)(m0 + m) * lda + kk];
                pa[r] = v;
                float4 u = make_float4(0.f, 0.f, 0.f, 0.f);
                if (kk < K && (n0 + m) < N) u = *(const float4*)&W[(size_t)(n0 + m) * ldw + kk];
                pb[r] = u;
            }
        }

        const float (*Ab)[BM + PAD] = As[buf];
        const float (*Bb)[BN + PAD] = Bs[buf];
        #pragma unroll
        for (int k = 0; k < BKK; k++) {
            float a[8], b[8];
            *(float4*)&a[0] = *(const float4*)&Ab[k][tm * 4];
            *(float4*)&a[4] = *(const float4*)&Ab[k][64 + tm * 4];
            *(float4*)&b[0] = *(const float4*)&Bb[k][tn * 4];
            *(float4*)&b[4] = *(const float4*)&Bb[k][64 + tn * 4];
            #pragma unroll
            for (int i = 0; i < 8; i++)
                #pragma unroll
                for (int j = 0; j < 8; j++)
                    acc[i][j] = fmaf(a[i], b[j], acc[i][j]);
        }
        __syncthreads();
    }

    #pragma unroll
    for (int ih = 0; ih < 2; ih++) {
        #pragma unroll
        for (int i4 = 0; i4 < 4; i4++) {
            int i = ih * 4 + i4;
            int m = m0 + ih * 64 + tm * 4 + i4;
            #pragma unroll
            for (int jh = 0; jh < 2; jh++) {
                int n = n0 + jh * 64 + tn * 4;
                if (n < N) {
                    float4 v = make_float4(acc[i][jh * 4 + 0], acc[i][jh * 4 + 1],
                                           acc[i][jh * 4 + 2], acc[i][jh * 4 + 3]);
                    if (mode == 1) {
                        float* vv = (float*)&v;
                        #pragma unroll
                        for (int j = 0; j < 4; j++) {
                            float z = vv[j] + bias[n + j];
                            vv[j] = fmaxf(z, 0.f) + log1pf(__expf(-fabsf(z)));
                        }
                    }
                    if (n + 3 < N) {
                        *(float4*)&C[(size_t)m * ldc + n] = v;
                    } else {
                        float* vv = (float*)&v;
                        #pragma unroll
                        for (int j = 0; j < 4; j++)
                            if (n + j < N) C[(size_t)m * ldc + n + j] = vv[j];
                    }
                }
            }
        }
    }
}

// ---------------- depthwise causal conv1d (k=4) + SiLU, smem-tiled ----------------
__global__ __launch_bounds__(256) void conv_silu2_kernel(const float* __restrict__ cw,
                                                         const float* __restrict__ cb,
                                                         const float* __restrict__ xz,
                                                         float* __restrict__ xc,
                                                         __half* __restrict__ xch) {
    __shared__ float sx[67][64];
    int d0 = blockIdx.x * 64;
    int mchunk = blockIdx.y;
    int l0 = (mchunk & 63) * 64;
    int b = mchunk >> 6;
    int tid = threadIdx.x;
    int tx = tid & 63, ty = tid >> 6;
    size_t rowbase = (size_t)b * L_SEQ;

    for (int r = ty; r < 67; r += 4) {
        int l = l0 - 3 + r;
        float v = 0.f;
        if (l >= 0) v = xz[(rowbase + l) * (2 * D_INNER) + d0 + tx];
        sx[r][tx] = v;
    }
    __syncthreads();

    int d = d0 + tx;
    float w0 = cw[d * 4 + 0], w1 = cw[d * 4 + 1];
    float w2 = cw[d * 4 + 2], w3 = cw[d * 4 + 3];
    float bias = cb[d];

    #pragma unroll 4
    for (int i = 0; i < 16; i++) {
        int ll = ty + i * 4;
        int r = ll + 3;
        float acc = bias;
        acc = fmaf(w3, sx[r][tx], acc);
        acc = fmaf(w2, sx[r - 1][tx], acc);
        acc = fmaf(w1, sx[r - 2][tx], acc);
        acc = fmaf(w0, sx[r - 3][tx], acc);
        float sg = 1.f / (1.f + __expf(-acc));
        float v = acc * sg;
        size_t o = (rowbase + l0 + ll) * D_INNER + d;
        xc[o] = v;
        xch[o] = __float2half_rn(v);
    }
}

// ---------------- selective scan v6: register-batched phases, 4-stage cp.async ----------------
// Per 16-step sub-chunk: parallel batch (loads + exp + f) into registers, then the pure
// FFMA recurrence (chain = 16 x 4 cyc), stores off-chain. Caps latency exposure.
#define SCH6 32
#define CH6 24
#define NST6 4
#define NCH6 (L_SEQ / SCH6)     // 128
#define S6_BC 0
#define S6_D  4096
#define S6_X  7168
#define S6_Z  10240
#define S6_P  13312
#define S6_TOTAL (13312 + 32 * 24 * 20)   // 28672 floats = 114688 B

__global__ __launch_bounds__(384) void scan6_kernel(const float* __restrict__ A_log,
                                                    const float* __restrict__ Dp,
                                                    const float* __restrict__ dtv,
                                                    const float* __restrict__ xc,
                                                    const float* __restrict__ xdbl,
                                                    const float* __restrict__ xz,
                                                    __half* __restrict__ yh) {
    extern __shared__ float sm6[];
    float* sBC = sm6 + S6_BC;
    float* sD  = sm6 + S6_D;
    float* sX  = sm6 + S6_X;
    float* sZ  = sm6 + S6_Z;
    float* sP  = sm6 + S6_P;

    int b = blockIdx.y;
    int g = blockIdx.x;
    int d0 = g * CH6;
    int tid = threadIdx.x;
    size_t bL = (size_t)b * L_SEQ;

    int lane = tid & 31;
    int w = tid >> 5;
    int half = lane >> 4;
    int n = lane & 15;
    int dl = 2 * w + half;

    float An = -__expf(A_log[(d0 + dl) * D_STATE + n]);
    float h = 0.f;

    int rl = tid / CH6;
    int rc = tid % CH6;
    float Dd = Dp[d0 + rc];

    auto issue = [&](int c) {
        int l0 = c * SCH6;
        int buf = c % NST6;
        uint32_t bcs = smem_u32(sBC + buf * 1024);
        uint32_t ds  = smem_u32(sD  + buf * 768);
        uint32_t xs  = smem_u32(sX  + buf * 768);
        uint32_t zs  = smem_u32(sZ  + buf * 768);
        for (int u = tid; u < 832; u += 384) {
            if (u < 256) {
                int l = u >> 3, c4 = u & 7;
                cpasync16(bcs + (uint32_t)(l * 32 + c4 * 4) * 4,
                          xdbl + (bL + l0 + l) * XPN + DT_RANK + c4 * 4, 16);
            } else if (u < 448) {
                int v = u - 256; int l = v / 6, c4 = v % 6;
                cpasync16(ds + (uint32_t)(l * 24 + c4 * 4) * 4,
                          dtv + (bL + l0 + l) * D_INNER + d0 + c4 * 4, 16);
            } else if (u < 640) {
                int v = u - 448; int l = v / 6, c4 = v % 6;
                cpasync16(xs + (uint32_t)(l * 24 + c4 * 4) * 4,
                          xc + (bL + l0 + l) * D_INNER + d0 + c4 * 4, 16);
            } else {
                int v = u - 640; int l = v / 6, c4 = v % 6;
                cpasync16(zs + (uint32_t)(l * 24 + c4 * 4) * 4,
                          xz + (bL + l0 + l) * 2 * D_INNER + D_INNER + d0 + c4 * 4, 16);
            }
        }
        cp_commit();
    };

    issue(0);
    issue(1);

    for (int c = 0; c < NCH6; c++) {
        if (c + 2 < NCH6) { issue(c + 2); cp_wait<2>(); }
        else if (c + 1 < NCH6) { cp_wait<1>(); }
        else { cp_wait<0>(); }
        __syncthreads();                 // BAR_a

        int buf = c % NST6;
        const float* bD  = sD  + buf * 768;
        const float* bX  = sX  + buf * 768;
        const float* bBC = sBC + buf * 1024;

        #pragma unroll
        for (int s = 0; s < 2; s++) {
            float ev[16], fv[16], cv[16];
            #pragma unroll
            for (int j = 0; j < 16; j++) {
                int l = s * 16 + j;
                float dt = bD[l * 24 + dl];
                float xv = bX[l * 24 + dl];
                float Bn = bBC[l * 32 + n];
                cv[j] = bBC[l * 32 + 16 + n];
                ev[j] = __expf(dt * An);
                fv[j] = dt * xv * Bn;
            }
            #pragma unroll
            for (int j = 0; j < 16; j++) {
                h = fmaf(ev[j], h, fv[j]);
                sP[((s * 16 + j) * 24 + dl) * 20 + n] = h * cv[j];
            }
        }
        __syncthreads();                 // BAR_b

        #pragma unroll
        for (int i = 0; i < 2; i++) {
            int l = rl + i * 16;
            const float* p = sP + (l * 24 + rc) * 20;
            float4 a  = *(const float4*)p;
            float4 bq = *(const float4*)(p + 4);
            float4 cq = *(const float4*)(p + 8);
            float4 dq = *(const float4*)(p + 12);
            float s = ((a.x + a.y) + (a.z + a.w)) + ((bq.x + bq.y) + (bq.z + bq.w))
                    + ((cq.x + cq.y) + (cq.z + cq.w)) + ((dq.x + dq.y) + (dq.z + dq.w));
            float xv = bX[l * 24 + rc];
            float zv = sZ[buf * 768 + l * 24 + rc];
            float yv = fmaf(xv, Dd, s);
            yv *= zv / (1.f + __expf(-zv));
            size_t o = (bL + (size_t)c * SCH6 + l) * D_INNER + d0 + rc;
            yh[o] = __float2half_rn(yv);
        }
    }
}

// ---------------- launch ----------------
extern "C" void kernel_launch(void* const* d_in, const int* in_sizes, int n_in,
                              void* d_out, int out_size) {
    const float* x          = (const float*)d_in[0];
    const float* ln_w       = (const float*)d_in[1];
    const float* ln_b       = (const float*)d_in[2];
    const float* in_proj_w  = (const float*)d_in[3];
    const float* conv_w     = (const float*)d_in[4];
    const float* conv_b     = (const float*)d_in[5];
    const float* x_proj_w   = (const float*)d_in[6];
    const float* dt_w       = (const float*)d_in[7];
    const float* dt_b       = (const float*)d_in[8];
    const float* A_log      = (const float*)d_in[9];
    const float* Dp         = (const float*)d_in[10];
    const float* out_proj_w = (const float*)d_in[11];
    float* out = (float*)d_out;

    float *p_xz, *p_xc, *p_xdbl, *p_dtv;
    __half *p_xnh, *p_xch, *p_yh;
    __half *p_wih, *p_wil, *p_woh, *p_wol, *p_wxh, *p_wxl;
    cudaGetSymbolAddress((void**)&p_xz,   g_xz);
    cudaGetSymbolAddress((void**)&p_xc,   g_xc);
    cudaGetSymbolAddress((void**)&p_xdbl, g_xdbl);
    cudaGetSymbolAddress((void**)&p_dtv,  g_dtv);
    cudaGetSymbolAddress((void**)&p_xnh,  g_xn_h);
    cudaGetSymbolAddress((void**)&p_xch,  g_xc_h);
    cudaGetSymbolAddress((void**)&p_yh,   g_y_h);
    cudaGetSymbolAddress((void**)&p_wih,  g_wi_hi);
    cudaGetSymbolAddress((void**)&p_wil,  g_wi_lo);
    cudaGetSymbolAddress((void**)&p_woh,  g_wo_hi);
    cudaGetSymbolAddress((void**)&p_wol,  g_wo_lo);
    cudaGetSymbolAddress((void**)&p_wxh,  g_wx_hi);
    cudaGetSymbolAddress((void**)&p_wxl,  g_wx_lo);

    const int SC_SMEM = S6_TOTAL * 4;   // 114688 B
    cudaFuncSetAttribute(mmagemm_kernel, cudaFuncAttributeMaxDynamicSharedMemorySize, MM_SMEM);
    cudaFuncSetAttribute(scan6_kernel, cudaFuncAttributeMaxDynamicSharedMemorySize, SC_SMEM);

    // 0) weight hi/lo conversion (single launch)
    int n4i = (2 * D_INNER * DIMC) / 4;
    int n4o = (DIMC * D_INNER) / 4;
    int n4x = (XPN * D_INNER) / 4;
    cvt3_kernel<<<(n4i + n4o + n4x + 255) / 256, 256>>>(
        in_proj_w, p_wih, p_wil, n4i,
        out_proj_w, p_woh, p_wol, n4o,
        x_proj_w, p_wxh, p_wxl, n4x);

    // 1) LayerNorm -> xn fp16
    ln_kernel<<<dim3(L_SEQ / 64, B_SZ), 256>>>(x, ln_w, ln_b, p_xnh);

    // 2) in_proj (fp16 2-term) — profiled slot (clock probe)
    mmagemm_kernel<<<dim3(2 * D_INNER / 128, M_TOTAL / 128), 256, MM_SMEM>>>(
        p_xnh, p_wih, p_wil, DIMC, 2 * D_INNER, p_xz, 2 * D_INNER, 0);

    // 3) depthwise conv + silu -> xc fp32 + fp16
    conv_silu2_kernel<<<dim3(D_INNER / 64, M_TOTAL / 64), 256>>>(
        conv_w, conv_b, p_xz, p_xc, p_xch);

    // 4) x_proj (fp16 2-term, N=56 masked)
    mmagemm_kernel<<<dim3(1, M_TOTAL / 128), 256, MM_SMEM>>>(
        p_xch, p_wxh, p_wxl, D_INNER, XPN, p_xdbl, XPN, 0);

    // 5) dt + softplus (fp32 SIMT, K=24)
    gemm2_kernel<<<dim3(D_INNER / BN, M_TOTAL / BM), 256>>>(
        p_xdbl, XPN, DT_RANK, dt_w, DT_RANK, D_INNER, p_dtv, D_INNER, 1, dt_b);

    // 6) selective scan v6 (register-batched) -> y fp16
    scan6_kernel<<<dim3(D_INNER / CH6, B_SZ), 384, SC_SMEM>>>(
        A_log, Dp, p_dtv, p_xc, p_xdbl, p_xz, p_yh);

    // 7) out_proj (fp16 2-term, transposed store)
    mmagemm_kernel<<<dim3(DIMC / 128, M_TOTAL / 128), 256, MM_SMEM>>>(
        p_yh, p_woh, p_wol, D_INNER, DIMC, out, 0, 2);
}

// round 15
// speedup vs baseline: 1.6584x; 1.0548x over previous
#include <cuda_runtime.h>
#include <cuda_fp16.h>
#include <cstdint>

#define B_SZ 4
#define DIMC 384
#define L_SEQ 4096
#define D_INNER 768
#define D_STATE 16
#define DT_RANK 24
#define XPN 56
#define M_TOTAL (B_SZ * L_SEQ)      // 16384

// ---------------- scratch (no allocations allowed) ----------------
__device__ float g_xz[(size_t)M_TOTAL * 2 * D_INNER];
__device__ float g_xc[(size_t)M_TOTAL * D_INNER];
__device__ float g_xdbl[(size_t)M_TOTAL * XPN];
__device__ float g_dtv[(size_t)M_TOTAL * D_INNER];

__device__ __half g_xn_h[(size_t)M_TOTAL * DIMC];
__device__ __half g_xc_h[(size_t)M_TOTAL * D_INNER];
__device__ __half g_y_h[(size_t)M_TOTAL * D_INNER];
__device__ __half g_wi_hi[(size_t)2 * D_INNER * DIMC];
__device__ __half g_wi_lo[(size_t)2 * D_INNER * DIMC];
__device__ __half g_wo_hi[(size_t)DIMC * D_INNER];
__device__ __half g_wo_lo[(size_t)DIMC * D_INNER];
__device__ __half g_wx_hi[(size_t)XPN * D_INNER];
__device__ __half g_wx_lo[(size_t)XPN * D_INNER];

// ---------------- small PTX helpers (all base-target, sm_80+) ----------------
__device__ __forceinline__ uint32_t smem_u32(const void* p) {
    uint32_t a;
    asm("{ .reg .u64 t; cvta.to.shared.u64 t, %1; cvt.u32.u64 %0, t; }" : "=r"(a) : "l"(p));
    return a;
}
__device__ __forceinline__ void cpasync16(uint32_t sa, const void* g, int sz) {
    asm volatile("cp.async.cg.shared.global [%0], [%1], 16, %2;" :: "r"(sa), "l"(g), "r"(sz) : "memory");
}
__device__ __forceinline__ void cp_commit() {
    asm volatile("cp.async.commit_group;" ::: "memory");
}
template <int N> __device__ __forceinline__ void cp_wait() {
    asm volatile("cp.async.wait_group %0;" :: "n"(N) : "memory");
}
__device__ __forceinline__ void ldsm4(uint32_t* r, uint32_t addr) {
    asm volatile("ldmatrix.sync.aligned.m8n8.x4.shared.b16 {%0,%1,%2,%3}, [%4];"
                 : "=r"(r[0]), "=r"(r[1]), "=r"(r[2]), "=r"(r[3]) : "r"(addr));
}
__device__ __forceinline__ void mma16816h(float* d, const uint32_t* a, const uint32_t* b) {
    asm volatile(
        "mma.sync.aligned.m16n8k16.row.col.f32.f16.f16.f32 "
        "{%0,%1,%2,%3}, {%4,%5,%6,%7}, {%8,%9}, {%0,%1,%2,%3};"
        : "+f"(d[0]), "+f"(d[1]), "+f"(d[2]), "+f"(d[3])
        : "r"(a[0]), "r"(a[1]), "r"(a[2]), "r"(a[3]), "r"(b[0]), "r"(b[1]));
}
__device__ __forceinline__ void bar_sync(int id, int cnt) {
    asm volatile("bar.sync %0, %1;" :: "r"(id), "r"(cnt) : "memory");
}
__device__ __forceinline__ void bar_arrive(int id, int cnt) {
    asm volatile("bar.arrive %0, %1;" :: "r"(id), "r"(cnt) : "memory");
}

// ---------------- fp16 2-term mma.sync GEMM (256 thr, 2 CTA/SM, 3-stage ring) ----------------
#define LDSROW 40
#define TILE_H (128 * LDSROW)       // 5120 halves
#define STAGE_B (3 * TILE_H * 2)    // 30720 B per stage
#define NST 3
#define MM_SMEM (NST * STAGE_B)     // 92160 B

__global__ __launch_bounds__(256, 2) void mmagemm_kernel(
    const __half* __restrict__ Ah,
    const __half* __restrict__ Bh, const __half* __restrict__ Bl,
    int K, int Nn, float* __restrict__ C, int ldc, int mode) {

    extern __shared__ __align__(16) uint8_t dsm[];
    uint32_t dsm_u = smem_u32(dsm);

    int tid = threadIdx.x;
    int wid = tid >> 5;
    int lane = tid & 31;
    int warp_m = wid & 1;
    int warp_n = wid >> 1;
    int m0 = blockIdx.y * 128;
    int n0 = blockIdx.x * 128;

    float acc[4][4][4];
    #pragma unroll
    for (int mt = 0; mt < 4; mt++)
        #pragma unroll
        for (int nt = 0; nt < 4; nt++)
            #pragma unroll
            for (int q = 0; q < 4; q++) acc[mt][nt][q] = 0.f;

    int nchunks = K >> 5;

    auto load_chunk = [&](int c) {
        int kc = c << 5;
        uint32_t sbase = dsm_u + (c % NST) * STAGE_B;
        #pragma unroll
        for (int i = 0; i < 6; i++) {
            int u = tid + i * 256;
            int tile = u >> 9;
            int v = u & 511;
            int row = v >> 2;
            int seg = v & 3;
            uint32_t sa = sbase + (tile * TILE_H + row * LDSROW + seg * 8) * 2;
            const __half* g;
            int sz = 16;
            if (tile == 0) {
                g = Ah + (size_t)(m0 + row) * K + kc + seg * 8;
            } else {
                int r = n0 + row;
                if (r >= Nn) { r = Nn - 1; sz = 0; }
                g = ((tile == 1) ? Bh : Bl) + (size_t)r * K + kc + seg * 8;
            }
            cpasync16(sa, g, sz);
        }
        cp_commit();
    };

    load_chunk(0);

    for (int c = 0; c < nchunks; c++) {
        if (c + 1 < nchunks) { load_chunk(c + 1); cp_wait<1>(); }
        else { cp_wait<0>(); }
        __syncthreads();

        uint32_t base = dsm_u + (c % NST) * STAGE_B;
        #pragma unroll
        for (int kk = 0; kk < 32; kk += 16) {
            uint32_t aF[4][4], bF[2][4][2];
            {
                int arow = warp_m * 64 + (lane & 15);
                int ak = kk + (lane >> 4) * 8;
                #pragma unroll
                for (int mt = 0; mt < 4; mt++)
                    ldsm4(aF[mt], base + ((arow + mt * 16) * LDSROW + ak) * 2);
            }
            {
                int brow = warp_n * 32 + (lane & 7) + (lane >> 4) * 8;
                int bk = kk + ((lane >> 3) & 1) * 8;
                #pragma unroll
                for (int hb = 0; hb < 2; hb++) {
                    uint32_t btile = (uint32_t)(1 + hb) * TILE_H * 2;
                    #pragma unroll
                    for (int g2 = 0; g2 < 2; g2++) {
                        uint32_t r[4];
                        ldsm4(r, base + btile + ((brow + g2 * 16) * LDSROW + bk) * 2);
                        bF[hb][g2 * 2][0] = r[0]; bF[hb][g2 * 2][1] = r[1];
                        bF[hb][g2 * 2 + 1][0] = r[2]; bF[hb][g2 * 2 + 1][1] = r[3];
                    }
                }
            }
            #pragma unroll
            for (int mt = 0; mt < 4; mt++)
                #pragma unroll
                for (int nt = 0; nt < 4; nt++) {
                    mma16816h(acc[mt][nt], aF[mt], bF[0][nt]);
                    mma16816h(acc[mt][nt], aF[mt], bF[1][nt]);
                }
        }
    }
    __syncthreads();

    if (mode == 0) {
        #pragma unroll
        for (int mt = 0; mt < 4; mt++) {
            int m = m0 + warp_m * 64 + mt * 16 + (lane >> 2);
            #pragma unroll
            for (int nt = 0; nt < 4; nt++) {
                int n = n0 + warp_n * 32 + nt * 8 + (lane & 3) * 2;
                if (n < Nn) {
                    float2 v0 = make_float2(acc[mt][nt][0], acc[mt][nt][1]);
                    float2 v1 = make_float2(acc[mt][nt][2], acc[mt][nt][3]);
                    *(float2*)&C[(size_t)m * ldc + n] = v0;
                    *(float2*)&C[(size_t)(m + 8) * ldc + n] = v1;
                }
            }
        }
    } else {
        float* sT = (float*)dsm;   // [128 n][132 m]
        #pragma unroll
        for (int mt = 0; mt < 4; mt++) {
            int ml = warp_m * 64 + mt * 16 + (lane >> 2);
            #pragma unroll
            for (int nt = 0; nt < 4; nt++) {
                int nl = warp_n * 32 + nt * 8 + (lane & 3) * 2;
                sT[nl * 132 + ml]           = acc[mt][nt][0];
                sT[(nl + 1) * 132 + ml]     = acc[mt][nt][1];
                sT[nl * 132 + ml + 8]       = acc[mt][nt][2];
                sT[(nl + 1) * 132 + ml + 8] = acc[mt][nt][3];
            }
        }
        __syncthreads();
        int b = m0 >> 12;
        int l0 = m0 & (L_SEQ - 1);
        int n = tid >> 1;
        int part = (tid & 1) * 64;
        float* dst = C + ((size_t)b * DIMC + n0 + n) * L_SEQ + l0 + part;
        const float* src = sT + n * 132 + part;
        #pragma unroll
        for (int q = 0; q < 16; q++)
            *(float4*)(dst + q * 4) = *(const float4*)(src + q * 4);
    }
}

// ---------------- fp32 -> fp16 hi/lo split for all three weights, one launch ----------------
__global__ __launch_bounds__(256) void cvt3_kernel(
    const float* __restrict__ s0, __half* __restrict__ hi0, __half* __restrict__ lo0, int n40,
    const float* __restrict__ s1, __half* __restrict__ hi1, __half* __restrict__ lo1, int n41,
    const float* __restrict__ s2, __half* __restrict__ hi2, __half* __restrict__ lo2, int n42) {
    int i = blockIdx.x * blockDim.x + threadIdx.x;
    const float* s; __half *hi, *lo;
    if (i < n40) { s = s0; hi = hi0; lo = lo0; }
    else if (i < n40 + n41) { i -= n40; s = s1; hi = hi1; lo = lo1; }
    else { i -= n40 + n41; if (i >= n42) return; s = s2; hi = hi2; lo = lo2; }
    float4 v = *(const float4*)(s + (size_t)i * 4);
    float vv[4] = {v.x, v.y, v.z, v.w};
    #pragma unroll
    for (int j = 0; j < 4; j++) {
        __half h = __float2half_rn(vv[j]);
        hi[(size_t)i * 4 + j] = h;
        lo[(size_t)i * 4 + j] = __float2half_rn(vv[j] - __half2float(h));
    }
}

// ---------------- LayerNorm: x (B,C,L) -> xn (B*L, C) fp16 ----------------
__global__ __launch_bounds__(256) void ln_kernel(const float* __restrict__ x,
                                                 const float* __restrict__ w,
                                                 const float* __restrict__ bsh,
                                                 __half* __restrict__ xnh) {
    int b  = blockIdx.y;
    int l0 = blockIdx.x * 64;
    int tid = threadIdx.x;
    int ll = tid & 63;
    int cg = tid >> 6;

    __shared__ float ssum[4][64];
    __shared__ float ssq[4][64];
    __shared__ float smean[64];
    __shared__ float srstd[64];
    __shared__ float st[16][65];

    const float* xb = x + (size_t)b * DIMC * L_SEQ;

    float s = 0.f, sq = 0.f;
    for (int c = cg; c < DIMC; c += 4) {
        float v = xb[(size_t)c * L_SEQ + l0 + ll];
        s += v; sq += v * v;
    }
    ssum[cg][ll] = s; ssq[cg][ll] = sq;
    __syncthreads();
    if (tid < 64) {
        float S = ssum[0][tid] + ssum[1][tid] + ssum[2][tid] + ssum[3][tid];
        float Q = ssq[0][tid] + ssq[1][tid] + ssq[2][tid] + ssq[3][tid];
        float mu = S * (1.f / DIMC);
        float var = Q * (1.f / DIMC) - mu * mu;
        smean[tid] = mu;
        srstd[tid] = rsqrtf(var + 1e-5f);
    }
    __syncthreads();

    for (int c0 = 0; c0 < DIMC; c0 += 16) {
        #pragma unroll
        for (int r = 0; r < 4; r++) {
            int c = c0 + cg + r * 4;
            float v = xb[(size_t)c * L_SEQ + l0 + ll];
            st[cg + r * 4][ll] = (v - smean[ll]) * srstd[ll] * w[c] + bsh[c];
        }
        __syncthreads();
        int c2 = tid & 15, lr = tid >> 4;
        #pragma unroll
        for (int p = 0; p < 4; p++) {
            int l = lr + p * 16;
            xnh[((size_t)b * L_SEQ + l0 + l) * DIMC + c0 + c2] = __float2half_rn(st[c2][l]);
        }
        __syncthreads();
    }
}

// ---------------- fp32 tiled GEMM (dt only) ----------------
#define BM 128
#define BN 128
#define BKK 16
#define PAD 4

__global__ __launch_bounds__(256, 2) void gemm2_kernel(
    const float* __restrict__ A, int lda, int K,
    const float* __restrict__ W, int ldw, int N,
    float* __restrict__ C, int ldc, int mode,
    const float* __restrict__ bias) {

    __shared__ float As[2][BKK][BM + PAD];
    __shared__ float Bs[2][BKK][BN + PAD];

    int tid = threadIdx.x;
    int m0 = blockIdx.y * BM;
    int n0 = blockIdx.x * BN;
    int tm = tid & 15;
    int tn = tid >> 4;

    int lr = tid >> 2;
    int lk = (tid & 3) * 4;

    float4 pa[2], pb[2];
    int nt = (K + BKK - 1) / BKK;

    {
        int kk = lk;
        #pragma unroll
        for (int r = 0; r < 2; r++) {
            int m = lr + r * 64;
            float4 v = make_float4(0.f, 0.f, 0.f, 0.f);
            if (kk < K) v = *(const float4*)&A[(size_t)(m0 + m) * lda + kk];
            pa[r] = v;
            float4 u = make_float4(0.f, 0.f, 0.f, 0.f);
            if (kk < K && (n0 + m) < N) u = *(const float4*)&W[(size_t)(n0 + m) * ldw + kk];
            pb[r] = u;
        }
    }

    float acc[8][8];
    #pragma unroll
    for (int i = 0; i < 8; i++)
        #pragma unroll
        for (int j = 0; j < 8; j++) acc[i][j] = 0.f;

    for (int t = 0; t < nt; t++) {
        int buf = t & 1;
        #pragma unroll
        for (int r = 0; r < 2; r++) {
            int m = lr + r * 64;
            As[buf][lk + 0][m] = pa[r].x;
            As[buf][lk + 1][m] = pa[r].y;
            As[buf][lk + 2][m] = pa[r].z;
            As[buf][lk + 3][m] = pa[r].w;
            Bs[buf][lk + 0][m] = pb[r].x;
            Bs[buf][lk + 1][m] = pb[r].y;
            Bs[buf][lk + 2][m] = pb[r].z;
            Bs[buf][lk + 3][m] = pb[r].w;
        }
        __syncthreads();

        if (t + 1 < nt) {
            int kk = (t + 1) * BKK + lk;
            #pragma unroll
            for (int r = 0; r < 2; r++) {
                int m = lr + r * 64;
                float4 v = make_float4(0.f, 0.f, 0.f, 0.f);
                if (kk < K) v = *(const float4*)&A[(size_t)(m0 + m) * lda + kk];
                pa[r] = v;
                float4 u = make_float4(0.f, 0.f, 0.f, 0.f);
                if (kk < K && (n0 + m) < N) u = *(const float4*)&W[(size_t)(n0 + m) * ldw + kk];
                pb[r] = u;
            }
        }

        const float (*Ab)[BM + PAD] = As[buf];
        const float (*Bb)[BN + PAD] = Bs[buf];
        #pragma unroll
        for (int k = 0; k < BKK; k++) {
            float a[8], b[8];
            *(float4*)&a[0] = *(const float4*)&Ab[k][tm * 4];
            *(float4*)&a[4] = *(const float4*)&Ab[k][64 + tm * 4];
            *(float4*)&b[0] = *(const float4*)&Bb[k][tn * 4];
            *(float4*)&b[4] = *(const float4*)&Bb[k][64 + tn * 4];
            #pragma unroll
            for (int i = 0; i < 8; i++)
                #pragma unroll
                for (int j = 0; j < 8; j++)
                    acc[i][j] = fmaf(a[i], b[j], acc[i][j]);
        }
        __syncthreads();
    }

    #pragma unroll
    for (int ih = 0; ih < 2; ih++) {
        #pragma unroll
        for (int i4 = 0; i4 < 4; i4++) {
            int i = ih * 4 + i4;
            int m = m0 + ih * 64 + tm * 4 + i4;
            #pragma unroll
            for (int jh = 0; jh < 2; jh++) {
                int n = n0 + jh * 64 + tn * 4;
                if (n < N) {
                    float4 v = make_float4(acc[i][jh * 4 + 0], acc[i][jh * 4 + 1],
                                           acc[i][jh * 4 + 2], acc[i][jh * 4 + 3]);
                    if (mode == 1) {
                        float* vv = (float*)&v;
                        #pragma unroll
                        for (int j = 0; j < 4; j++) {
                            float z = vv[j] + bias[n + j];
                            vv[j] = fmaxf(z, 0.f) + log1pf(__expf(-fabsf(z)));
                        }
                    }
                    if (n + 3 < N) {
                        *(float4*)&C[(size_t)m * ldc + n] = v;
                    } else {
                        float* vv = (float*)&v;
                        #pragma unroll
                        for (int j = 0; j < 4; j++)
                            if (n + j < N) C[(size_t)m * ldc + n + j] = vv[j];
                    }
                }
            }
        }
    }
}

// ---------------- depthwise causal conv1d (k=4) + SiLU, smem-tiled ----------------
__global__ __launch_bounds__(256) void conv_silu2_kernel(const float* __restrict__ cw,
                                                         const float* __restrict__ cb,
                                                         const float* __restrict__ xz,
                                                         float* __restrict__ xc,
                                                         __half* __restrict__ xch) {
    __shared__ float sx[67][64];
    int d0 = blockIdx.x * 64;
    int mchunk = blockIdx.y;
    int l0 = (mchunk & 63) * 64;
    int b = mchunk >> 6;
    int tid = threadIdx.x;
    int tx = tid & 63, ty = tid >> 6;
    size_t rowbase = (size_t)b * L_SEQ;

    for (int r = ty; r < 67; r += 4) {
        int l = l0 - 3 + r;
        float v = 0.f;
        if (l >= 0) v = xz[(rowbase + l) * (2 * D_INNER) + d0 + tx];
        sx[r][tx] = v;
    }
    __syncthreads();

    int d = d0 + tx;
    float w0 = cw[d * 4 + 0], w1 = cw[d * 4 + 1];
    float w2 = cw[d * 4 + 2], w3 = cw[d * 4 + 3];
    float bias = cb[d];

    #pragma unroll 4
    for (int i = 0; i < 16; i++) {
        int ll = ty + i * 4;
        int r = ll + 3;
        float acc = bias;
        acc = fmaf(w3, sx[r][tx], acc);
        acc = fmaf(w2, sx[r - 1][tx], acc);
        acc = fmaf(w1, sx[r - 2][tx], acc);
        acc = fmaf(w0, sx[r - 3][tx], acc);
        float sg = 1.f / (1.f + __expf(-acc));
        float v = acc * sg;
        size_t o = (rowbase + l0 + ll) * D_INNER + d;
        xc[o] = v;
        xch[o] = __float2half_rn(v);
    }
}

// ---------------- selective scan v7: warp-specialized producer/consumer ----------------
// 512 threads: warps 0-11 (384 thr) scan; warps 12-15 (128 thr) reduce+gate+store.
// Named barriers, parity-alternated to avoid generation aliasing:
//   FULL(p)=1+p : scan arrives (384) after writing sP[p]; reduce syncs (total 512)
//   DONE(p)=3+p : reduce arrives (128) after consuming chunk; scan syncs (total 512)
//   id 5        : scan-internal (384) publish of cp.async stage data
// sP double-buffered; 4-stage input ring. Ring-reuse: issue(c+2) overwrites stage
// (c+2)%4, last read by reduce(c-2); scan syncs DONE(c&1) (= reduce(c-2) done)
// BEFORE issuing, so the overwrite is ordered after all reads.
#define SCH7 32
#define CH7 24
#define NST7 4
#define NCH7 (L_SEQ / SCH7)     // 128
// float offsets
#define S7_BC 0                           // 4*32*32   = 4096
#define S7_D  4096                        // 4*32*24   = 3072
#define S7_X  7168
#define S7_Z  10240
#define S7_P  13312                       // 2*32*24*20 = 30720
#define S7_TOTAL (13312 + 2 * 32 * 24 * 20)   // 44032 floats = 176128 B

__global__ __launch_bounds__(512) void scan7_kernel(const float* __restrict__ A_log,
                                                    const float* __restrict__ Dp,
                                                    const float* __restrict__ dtv,
                                                    const float* __restrict__ xc,
                                                    const float* __restrict__ xdbl,
                                                    const float* __restrict__ xz,
                                                    __half* __restrict__ yh) {
    extern __shared__ float sm7[];
    float* sBC = sm7 + S7_BC;
    float* sD  = sm7 + S7_D;
    float* sX  = sm7 + S7_X;
    float* sZ  = sm7 + S7_Z;
    float* sP  = sm7 + S7_P;

    int b = blockIdx.y;
    int g = blockIdx.x;
    int d0 = g * CH7;
    int tid = threadIdx.x;
    size_t bL = (size_t)b * L_SEQ;

    if (tid < 384) {
        // -------- scan group --------
        int lane = tid & 31;
        int w = tid >> 5;
        int half = lane >> 4;
        int n = lane & 15;
        int dl = 2 * w + half;

        float An = -__expf(A_log[(d0 + dl) * D_STATE + n]);
        float h = 0.f;

        auto issue = [&](int c) {
            int l0 = c * SCH7;
            int buf = c % NST7;
            uint32_t bcs = smem_u32(sBC + buf * 1024);
            uint32_t ds  = smem_u32(sD  + buf * 768);
            uint32_t xs  = smem_u32(sX  + buf * 768);
            uint32_t zs  = smem_u32(sZ  + buf * 768);
            for (int u = tid; u < 832; u += 384) {
                if (u < 256) {
                    int l = u >> 3, c4 = u & 7;
                    cpasync16(bcs + (uint32_t)(l * 32 + c4 * 4) * 4,
                              xdbl + (bL + l0 + l) * XPN + DT_RANK + c4 * 4, 16);
                } else if (u < 448) {
                    int v = u - 256; int l = v / 6, c4 = v % 6;
                    cpasync16(ds + (uint32_t)(l * 24 + c4 * 4) * 4,
                              dtv + (bL + l0 + l) * D_INNER + d0 + c4 * 4, 16);
                } else if (u < 640) {
                    int v = u - 448; int l = v / 6, c4 = v % 6;
                    cpasync16(xs + (uint32_t)(l * 24 + c4 * 4) * 4,
                              xc + (bL + l0 + l) * D_INNER + d0 + c4 * 4, 16);
                } else {
                    int v = u - 640; int l = v / 6, c4 = v % 6;
                    cpasync16(zs + (uint32_t)(l * 24 + c4 * 4) * 4,
                              xz + (bL + l0 + l) * 2 * D_INNER + D_INNER + d0 + c4 * 4, 16);
                }
            }
            cp_commit();
        };

        issue(0);
        issue(1);

        for (int c = 0; c < NCH7; c++) {
            if (c >= 2) bar_sync(3 + (c & 1), 512);      // reduce(c-2) done
            if (c + 2 < NCH7) { issue(c + 2); cp_wait<2>(); }
            else if (c + 1 < NCH7) { cp_wait<1>(); }
            else { cp_wait<0>(); }
            bar_sync(5, 384);                             // publish stage c%4 to scan group

            int buf = c % NST7;
            const float* bD  = sD  + buf * 768;
            const float* bX  = sX  + buf * 768;
            const float* bBC = sBC + buf * 1024;
            float* pS = sP + (c & 1) * 15360;

            #pragma unroll
            for (int s = 0; s < 2; s++) {
                float ev[16], fv[16], cv[16];
                #pragma unroll
                for (int j = 0; j < 16; j++) {
                    int l = s * 16 + j;
                    float dt = bD[l * 24 + dl];
                    float xv = bX[l * 24 + dl];
                    float Bn = bBC[l * 32 + n];
                    cv[j] = bBC[l * 32 + 16 + n];
                    ev[j] = __expf(dt * An);
                    fv[j] = dt * xv * Bn;
                }
                #pragma unroll
                for (int j = 0; j < 16; j++) {
                    h = fmaf(ev[j], h, fv[j]);
                    pS[((s * 16 + j) * 24 + dl) * 20 + n] = h * cv[j];
                }
            }
            bar_arrive(1 + (c & 1), 512);                 // sP[c&1] full
        }
    } else {
        // -------- reduce group (128 threads) --------
        int rt = tid - 384;
        float Dd[6];
        #pragma unroll
        for (int k = 0; k < 6; k++)
            Dd[k] = Dp[d0 + (rt + 128 * k) % 24];

        for (int c = 0; c < NCH7; c++) {
            bar_sync(1 + (c & 1), 512);                   // wait sP[c&1] full
            int buf = c % NST7;
            const float* bX = sX + buf * 768;
            const float* bZ = sZ + buf * 768;
            const float* pS = sP + (c & 1) * 15360;

            #pragma unroll
            for (int k = 0; k < 6; k++) {
                int u = rt + 128 * k;
                const float* p = pS + u * 20;
                float4 a  = *(const float4*)p;
                float4 bq = *(const float4*)(p + 4);
                float4 cq = *(const float4*)(p + 8);
                float4 dq = *(const float4*)(p + 12);
                float s = ((a.x + a.y) + (a.z + a.w)) + ((bq.x + bq.y) + (bq.z + bq.w))
                        + ((cq.x + cq.y) + (cq.z + cq.w)) + ((dq.x + dq.y) + (dq.z + dq.w));
                float xv = bX[u];
                float zv = bZ[u];
                float yv = fmaf(xv, Dd[k], s);
                yv *= zv / (1.f + __expf(-zv));
                int l = u / 24, ch = u % 24;
                yh[(bL + (size_t)c * SCH7 + l) * D_INNER + d0 + ch] = __float2half_rn(yv);
            }
            bar_arrive(3 + (c & 1), 512);                 // chunk c consumed
        }
    }
}

// ---------------- launch ----------------
extern "C" void kernel_launch(void* const* d_in, const int* in_sizes, int n_in,
                              void* d_out, int out_size) {
    const float* x          = (const float*)d_in[0];
    const float* ln_w       = (const float*)d_in[1];
    const float* ln_b       = (const float*)d_in[2];
    const float* in_proj_w  = (const float*)d_in[3];
    const float* conv_w     = (const float*)d_in[4];
    const float* conv_b     = (const float*)d_in[5];
    const float* x_proj_w   = (const float*)d_in[6];
    const float* dt_w       = (const float*)d_in[7];
    const float* dt_b       = (const float*)d_in[8];
    const float* A_log      = (const float*)d_in[9];
    const float* Dp         = (const float*)d_in[10];
    const float* out_proj_w = (const float*)d_in[11];
    float* out = (float*)d_out;

    float *p_xz, *p_xc, *p_xdbl, *p_dtv;
    __half *p_xnh, *p_xch, *p_yh;
    __half *p_wih, *p_wil, *p_woh, *p_wol, *p_wxh, *p_wxl;
    cudaGetSymbolAddress((void**)&p_xz,   g_xz);
    cudaGetSymbolAddress((void**)&p_xc,   g_xc);
    cudaGetSymbolAddress((void**)&p_xdbl, g_xdbl);
    cudaGetSymbolAddress((void**)&p_dtv,  g_dtv);
    cudaGetSymbolAddress((void**)&p_xnh,  g_xn_h);
    cudaGetSymbolAddress((void**)&p_xch,  g_xc_h);
    cudaGetSymbolAddress((void**)&p_yh,   g_y_h);
    cudaGetSymbolAddress((void**)&p_wih,  g_wi_hi);
    cudaGetSymbolAddress((void**)&p_wil,  g_wi_lo);
    cudaGetSymbolAddress((void**)&p_woh,  g_wo_hi);
    cudaGetSymbolAddress((void**)&p_wol,  g_wo_lo);
    cudaGetSymbolAddress((void**)&p_wxh,  g_wx_hi);
    cudaGetSymbolAddress((void**)&p_wxl,  g_wx_lo);

    const int SC_SMEM = S7_TOTAL * 4;   // 176128 B
    cudaFuncSetAttribute(mmagemm_kernel, cudaFuncAttributeMaxDynamicSharedMemorySize, MM_SMEM);
    cudaFuncSetAttribute(scan7_kernel, cudaFuncAttributeMaxDynamicSharedMemorySize, SC_SMEM);

    // 0) weight hi/lo conversion (single launch)
    int n4i = (2 * D_INNER * DIMC) / 4;
    int n4o = (DIMC * D_INNER) / 4;
    int n4x = (XPN * D_INNER) / 4;
    cvt3_kernel<<<(n4i + n4o + n4x + 255) / 256, 256>>>(
        in_proj_w, p_wih, p_wil, n4i,
        out_proj_w, p_woh, p_wol, n4o,
        x_proj_w, p_wxh, p_wxl, n4x);

    // 1) LayerNorm -> xn fp16
    ln_kernel<<<dim3(L_SEQ / 64, B_SZ), 256>>>(x, ln_w, ln_b, p_xnh);

    // 2) in_proj (fp16 2-term) — profiled slot (clock probe)
    mmagemm_kernel<<<dim3(2 * D_INNER / 128, M_TOTAL / 128), 256, MM_SMEM>>>(
        p_xnh, p_wih, p_wil, DIMC, 2 * D_INNER, p_xz, 2 * D_INNER, 0);

    // 3) depthwise conv + silu -> xc fp32 + fp16
    conv_silu2_kernel<<<dim3(D_INNER / 64, M_TOTAL / 64), 256>>>(
        conv_w, conv_b, p_xz, p_xc, p_xch);

    // 4) x_proj (fp16 2-term, N=56 masked)
    mmagemm_kernel<<<dim3(1, M_TOTAL / 128), 256, MM_SMEM>>>(
        p_xch, p_wxh, p_wxl, D_INNER, XPN, p_xdbl, XPN, 0);

    // 5) dt + softplus (fp32 SIMT, K=24)
    gemm2_kernel<<<dim3(D_INNER / BN, M_TOTAL / BM), 256>>>(
        p_xdbl, XPN, DT_RANK, dt_w, DT_RANK, D_INNER, p_dtv, D_INNER, 1, dt_b);

    // 6) selective scan v7 (warp-specialized) -> y fp16
    scan7_kernel<<<dim3(D_INNER / CH7, B_SZ), 512, SC_SMEM>>>(
        A_log, Dp, p_dtv, p_xc, p_xdbl, p_xz, p_yh);

    // 7) out_proj (fp16 2-term, transposed store)
    mmagemm_kernel<<<dim3(DIMC / 128, M_TOTAL / 128), 256, MM_SMEM>>>(
        p_yh, p_woh, p_wol, D_INNER, DIMC, out, 0, 2);
}

// round 16
// speedup vs baseline: 1.7076x; 1.0297x over previous
#include <cuda_runtime.h>
#include <cuda_fp16.h>
#include <cstdint>

#define B_SZ 4
#define DIMC 384
#define L_SEQ 4096
#define D_INNER 768
#define D_STATE 16
#define DT_RANK 24
#define XPN 56
#define M_TOTAL (B_SZ * L_SEQ)      // 16384

// ---------------- scratch (no allocations allowed) ----------------
__device__ float g_xq[(size_t)M_TOTAL * D_INNER];     // in_proj x-half, fp32
__device__ float g_xdbl[(size_t)M_TOTAL * XPN];
__device__ float g_dtv[(size_t)M_TOTAL * D_INNER];

__device__ __half g_z_h[(size_t)M_TOTAL * D_INNER];  // in_proj z-half, fp16
__device__ __half g_xn_h[(size_t)M_TOTAL * DIMC];
__device__ __half g_xc_h[(size_t)M_TOTAL * D_INNER];
__device__ __half g_y_h[(size_t)M_TOTAL * D_INNER];
__device__ __half g_wi_hi[(size_t)2 * D_INNER * DIMC];
__device__ __half g_wi_lo[(size_t)2 * D_INNER * DIMC];
__device__ __half g_wo_hi[(size_t)DIMC * D_INNER];
__device__ __half g_wo_lo[(size_t)DIMC * D_INNER];
__device__ __half g_wx_hi[(size_t)XPN * D_INNER];
__device__ __half g_wx_lo[(size_t)XPN * D_INNER];

// ---------------- small PTX helpers (all base-target, sm_80+) ----------------
__device__ __forceinline__ uint32_t smem_u32(const void* p) {
    uint32_t a;
    asm("{ .reg .u64 t; cvta.to.shared.u64 t, %1; cvt.u32.u64 %0, t; }" : "=r"(a) : "l"(p));
    return a;
}
__device__ __forceinline__ void cpasync16(uint32_t sa, const void* g, int sz) {
    asm volatile("cp.async.cg.shared.global [%0], [%1], 16, %2;" :: "r"(sa), "l"(g), "r"(sz) : "memory");
}
__device__ __forceinline__ void cp_commit() {
    asm volatile("cp.async.commit_group;" ::: "memory");
}
template <int N> __device__ __forceinline__ void cp_wait() {
    asm volatile("cp.async.wait_group %0;" :: "n"(N) : "memory");
}
__device__ __forceinline__ void ldsm4(uint32_t* r, uint32_t addr) {
    asm volatile("ldmatrix.sync.aligned.m8n8.x4.shared.b16 {%0,%1,%2,%3}, [%4];"
                 : "=r"(r[0]), "=r"(r[1]), "=r"(r[2]), "=r"(r[3]) : "r"(addr));
}
__device__ __forceinline__ void mma16816h(float* d, const uint32_t* a, const uint32_t* b) {
    asm volatile(
        "mma.sync.aligned.m16n8k16.row.col.f32.f16.f16.f32 "
        "{%0,%1,%2,%3}, {%4,%5,%6,%7}, {%8,%9}, {%0,%1,%2,%3};"
        : "+f"(d[0]), "+f"(d[1]), "+f"(d[2]), "+f"(d[3])
        : "r"(a[0]), "r"(a[1]), "r"(a[2]), "r"(a[3]), "r"(b[0]), "r"(b[1]));
}
__device__ __forceinline__ void bar_sync(int id, int cnt) {
    asm volatile("bar.sync %0, %1;" :: "r"(id), "r"(cnt) : "memory");
}
__device__ __forceinline__ void bar_arrive(int id, int cnt) {
    asm volatile("bar.arrive %0, %1;" :: "r"(id), "r"(cnt) : "memory");
}

// ---------------- fp16 2-term mma.sync GEMM (256 thr, 2 CTA/SM, 3-stage ring) ----------------
// mode 0: fp32 C[m*ldc+n] (mask n<Nn)
// mode 2: transposed fp32 store out[(b*DIMC+n)*L_SEQ+l]
// mode 3: split store — n<768 -> fp32 C[m*768+n]; n>=768 -> fp16 Ch[m*768+n-768]
#define LDSROW 40
#define TILE_H (128 * LDSROW)       // 5120 halves
#define STAGE_B (3 * TILE_H * 2)    // 30720 B per stage
#define NST 3
#define MM_SMEM (NST * STAGE_B)     // 92160 B

__global__ __launch_bounds__(256, 2) void mmagemm_kernel(
    const __half* __restrict__ Ah,
    const __half* __restrict__ Bh, const __half* __restrict__ Bl,
    int K, int Nn, float* __restrict__ C, __half* __restrict__ Ch,
    int ldc, int mode) {

    extern __shared__ __align__(16) uint8_t dsm[];
    uint32_t dsm_u = smem_u32(dsm);

    int tid = threadIdx.x;
    int wid = tid >> 5;
    int lane = tid & 31;
    int warp_m = wid & 1;
    int warp_n = wid >> 1;
    int m0 = blockIdx.y * 128;
    int n0 = blockIdx.x * 128;

    float acc[4][4][4];
    #pragma unroll
    for (int mt = 0; mt < 4; mt++)
        #pragma unroll
        for (int nt = 0; nt < 4; nt++)
            #pragma unroll
            for (int q = 0; q < 4; q++) acc[mt][nt][q] = 0.f;

    int nchunks = K >> 5;

    auto load_chunk = [&](int c) {
        int kc = c << 5;
        uint32_t sbase = dsm_u + (c % NST) * STAGE_B;
        #pragma unroll
        for (int i = 0; i < 6; i++) {
            int u = tid + i * 256;
            int tile = u >> 9;
            int v = u & 511;
            int row = v >> 2;
            int seg = v & 3;
            uint32_t sa = sbase + (tile * TILE_H + row * LDSROW + seg * 8) * 2;
            const __half* g;
            int sz = 16;
            if (tile == 0) {
                g = Ah + (size_t)(m0 + row) * K + kc + seg * 8;
            } else {
                int r = n0 + row;
                if (r >= Nn) { r = Nn - 1; sz = 0; }
                g = ((tile == 1) ? Bh : Bl) + (size_t)r * K + kc + seg * 8;
            }
            cpasync16(sa, g, sz);
        }
        cp_commit();
    };

    load_chunk(0);

    for (int c = 0; c < nchunks; c++) {
        if (c + 1 < nchunks) { load_chunk(c + 1); cp_wait<1>(); }
        else { cp_wait<0>(); }
        __syncthreads();

        uint32_t base = dsm_u + (c % NST) * STAGE_B;
        #pragma unroll
        for (int kk = 0; kk < 32; kk += 16) {
            uint32_t aF[4][4], bF[2][4][2];
            {
                int arow = warp_m * 64 + (lane & 15);
                int ak = kk + (lane >> 4) * 8;
                #pragma unroll
                for (int mt = 0; mt < 4; mt++)
                    ldsm4(aF[mt], base + ((arow + mt * 16) * LDSROW + ak) * 2);
            }
            {
                int brow = warp_n * 32 + (lane & 7) + (lane >> 4) * 8;
                int bk = kk + ((lane >> 3) & 1) * 8;
                #pragma unroll
                for (int hb = 0; hb < 2; hb++) {
                    uint32_t btile = (uint32_t)(1 + hb) * TILE_H * 2;
                    #pragma unroll
                    for (int g2 = 0; g2 < 2; g2++) {
                        uint32_t r[4];
                        ldsm4(r, base + btile + ((brow + g2 * 16) * LDSROW + bk) * 2);
                        bF[hb][g2 * 2][0] = r[0]; bF[hb][g2 * 2][1] = r[1];
                        bF[hb][g2 * 2 + 1][0] = r[2]; bF[hb][g2 * 2 + 1][1] = r[3];
                    }
                }
            }
            #pragma unroll
            for (int mt = 0; mt < 4; mt++)
                #pragma unroll
                for (int nt = 0; nt < 4; nt++) {
                    mma16816h(acc[mt][nt], aF[mt], bF[0][nt]);
                    mma16816h(acc[mt][nt], aF[mt], bF[1][nt]);
                }
        }
    }
    __syncthreads();

    if (mode == 0) {
        #pragma unroll
        for (int mt = 0; mt < 4; mt++) {
            int m = m0 + warp_m * 64 + mt * 16 + (lane >> 2);
            #pragma unroll
            for (int nt = 0; nt < 4; nt++) {
                int n = n0 + warp_n * 32 + nt * 8 + (lane & 3) * 2;
                if (n < Nn) {
                    *(float2*)&C[(size_t)m * ldc + n] = make_float2(acc[mt][nt][0], acc[mt][nt][1]);
                    *(float2*)&C[(size_t)(m + 8) * ldc + n] = make_float2(acc[mt][nt][2], acc[mt][nt][3]);
                }
            }
        }
    } else if (mode == 3) {
        bool zhalf = (n0 >= D_INNER);
        #pragma unroll
        for (int mt = 0; mt < 4; mt++) {
            int m = m0 + warp_m * 64 + mt * 16 + (lane >> 2);
            #pragma unroll
            for (int nt = 0; nt < 4; nt++) {
                int n = n0 + warp_n * 32 + nt * 8 + (lane & 3) * 2;
                if (!zhalf) {
                    *(float2*)&C[(size_t)m * D_INNER + n] = make_float2(acc[mt][nt][0], acc[mt][nt][1]);
                    *(float2*)&C[(size_t)(m + 8) * D_INNER + n] = make_float2(acc[mt][nt][2], acc[mt][nt][3]);
                } else {
                    int nz = n - D_INNER;
                    *(__half2*)&Ch[(size_t)m * D_INNER + nz] = __floats2half2_rn(acc[mt][nt][0], acc[mt][nt][1]);
                    *(__half2*)&Ch[(size_t)(m + 8) * D_INNER + nz] = __floats2half2_rn(acc[mt][nt][2], acc[mt][nt][3]);
                }
            }
        }
    } else {
        float* sT = (float*)dsm;   // [128 n][132 m]
        #pragma unroll
        for (int mt = 0; mt < 4; mt++) {
            int ml = warp_m * 64 + mt * 16 + (lane >> 2);
            #pragma unroll
            for (int nt = 0; nt < 4; nt++) {
                int nl = warp_n * 32 + nt * 8 + (lane & 3) * 2;
                sT[nl * 132 + ml]           = acc[mt][nt][0];
                sT[(nl + 1) * 132 + ml]     = acc[mt][nt][1];
                sT[nl * 132 + ml + 8]       = acc[mt][nt][2];
                sT[(nl + 1) * 132 + ml + 8] = acc[mt][nt][3];
            }
        }
        __syncthreads();
        int b = m0 >> 12;
        int l0 = m0 & (L_SEQ - 1);
        int n = tid >> 1;
        int part = (tid & 1) * 64;
        float* dst = C + ((size_t)b * DIMC + n0 + n) * L_SEQ + l0 + part;
        const float* src = sT + n * 132 + part;
        #pragma unroll
        for (int q = 0; q < 16; q++)
            *(float4*)(dst + q * 4) = *(const float4*)(src + q * 4);
    }
}

// ---------------- fp32 -> fp16 hi/lo split for all three weights, one launch ----------------
__global__ __launch_bounds__(256) void cvt3_kernel(
    const float* __restrict__ s0, __half* __restrict__ hi0, __half* __restrict__ lo0, int n40,
    const float* __restrict__ s1, __half* __restrict__ hi1, __half* __restrict__ lo1, int n41,
    const float* __restrict__ s2, __half* __restrict__ hi2, __half* __restrict__ lo2, int n42) {
    int i = blockIdx.x * blockDim.x + threadIdx.x;
    const float* s; __half *hi, *lo;
    if (i < n40) { s = s0; hi = hi0; lo = lo0; }
    else if (i < n40 + n41) { i -= n40; s = s1; hi = hi1; lo = lo1; }
    else { i -= n40 + n41; if (i >= n42) return; s = s2; hi = hi2; lo = lo2; }
    float4 v = *(const float4*)(s + (size_t)i * 4);
    float vv[4] = {v.x, v.y, v.z, v.w};
    #pragma unroll
    for (int j = 0; j < 4; j++) {
        __half h = __float2half_rn(vv[j]);
        hi[(size_t)i * 4 + j] = h;
        lo[(size_t)i * 4 + j] = __float2half_rn(vv[j] - __half2float(h));
    }
}

// ---------------- LayerNorm: x (B,C,L) -> xn (B*L, C) fp16 ----------------
__global__ __launch_bounds__(256) void ln_kernel(const float* __restrict__ x,
                                                 const float* __restrict__ w,
                                                 const float* __restrict__ bsh,
                                                 __half* __restrict__ xnh) {
    int b  = blockIdx.y;
    int l0 = blockIdx.x * 64;
    int tid = threadIdx.x;
    int ll = tid & 63;
    int cg = tid >> 6;

    __shared__ float ssum[4][64];
    __shared__ float ssq[4][64];
    __shared__ float smean[64];
    __shared__ float srstd[64];
    __shared__ float st[16][65];

    const float* xb = x + (size_t)b * DIMC * L_SEQ;

    float s = 0.f, sq = 0.f;
    for (int c = cg; c < DIMC; c += 4) {
        float v = xb[(size_t)c * L_SEQ + l0 + ll];
        s += v; sq += v * v;
    }
    ssum[cg][ll] = s; ssq[cg][ll] = sq;
    __syncthreads();
    if (tid < 64) {
        float S = ssum[0][tid] + ssum[1][tid] + ssum[2][tid] + ssum[3][tid];
        float Q = ssq[0][tid] + ssq[1][tid] + ssq[2][tid] + ssq[3][tid];
        float mu = S * (1.f / DIMC);
        float var = Q * (1.f / DIMC) - mu * mu;
        smean[tid] = mu;
        srstd[tid] = rsqrtf(var + 1e-5f);
    }
    __syncthreads();

    for (int c0 = 0; c0 < DIMC; c0 += 16) {
        #pragma unroll
        for (int r = 0; r < 4; r++) {
            int c = c0 + cg + r * 4;
            float v = xb[(size_t)c * L_SEQ + l0 + ll];
            st[cg + r * 4][ll] = (v - smean[ll]) * srstd[ll] * w[c] + bsh[c];
        }
        __syncthreads();
        int c2 = tid & 15, lr = tid >> 4;
        #pragma unroll
        for (int p = 0; p < 4; p++) {
            int l = lr + p * 16;
            xnh[((size_t)b * L_SEQ + l0 + l) * DIMC + c0 + c2] = __float2half_rn(st[c2][l]);
        }
        __syncthreads();
    }
}

// ---------------- fp32 tiled GEMM (dt only) ----------------
#define BM 128
#define BN 128
#define BKK 16
#define PAD 4

__global__ __launch_bounds__(256, 2) void gemm2_kernel(
    const float* __restrict__ A, int lda, int K,
    const float* __restrict__ W, int ldw, int N,
    float* __restrict__ C, int ldc, int mode,
    const float* __restrict__ bias) {

    __shared__ float As[2][BKK][BM + PAD];
    __shared__ float Bs[2][BKK][BN + PAD];

    int tid = threadIdx.x;
    int m0 = blockIdx.y * BM;
    int n0 = blockIdx.x * BN;
    int tm = tid & 15;
    int tn = tid >> 4;

    int lr = tid >> 2;
    int lk = (tid & 3) * 4;

    float4 pa[2], pb[2];
    int nt = (K + BKK - 1) / BKK;

    {
        int kk = lk;
        #pragma unroll
        for (int r = 0; r < 2; r++) {
            int m = lr + r * 64;
            float4 v = make_float4(0.f, 0.f, 0.f, 0.f);
            if (kk < K) v = *(const float4*)&A[(size_t)(m0 + m) * lda + kk];
            pa[r] = v;
            float4 u = make_float4(0.f, 0.f, 0.f, 0.f);
            if (kk < K && (n0 + m) < N) u = *(const float4*)&W[(size_t)(n0 + m) * ldw + kk];
            pb[r] = u;
        }
    }

    float acc[8][8];
    #pragma unroll
    for (int i = 0; i < 8; i++)
        #pragma unroll
        for (int j = 0; j < 8; j++) acc[i][j] = 0.f;

    for (int t = 0; t < nt; t++) {
        int buf = t & 1;
        #pragma unroll
        for (int r = 0; r < 2; r++) {
            int m = lr + r * 64;
            As[buf][lk + 0][m] = pa[r].x;
            As[buf][lk + 1][m] = pa[r].y;
            As[buf][lk + 2][m] = pa[r].z;
            As[buf][lk + 3][m] = pa[r].w;
            Bs[buf][lk + 0][m] = pb[r].x;
            Bs[buf][lk + 1][m] = pb[r].y;
            Bs[buf][lk + 2][m] = pb[r].z;
            Bs[buf][lk + 3][m] = pb[r].w;
        }
        __syncthreads();

        if (t + 1 < nt) {
            int kk = (t + 1) * BKK + lk;
            #pragma unroll
            for (int r = 0; r < 2; r++) {
                int m = lr + r * 64;
                float4 v = make_float4(0.f, 0.f, 0.f, 0.f);
                if (kk < K) v = *(const float4*)&A[(size_t)(m0 + m) * lda + kk];
                pa[r] = v;
                float4 u = make_float4(0.f, 0.f, 0.f, 0.f);
                if (kk < K && (n0 + m) < N) u = *(const float4*)&W[(size_t)(n0 + m) * ldw + kk];
                pb[r] = u;
            }
        }

        const float (*Ab)[BM + PAD] = As[buf];
        const float (*Bb)[BN + PAD] = Bs[buf];
        #pragma unroll
        for (int k = 0; k < BKK; k++) {
            float a[8], b[8];
            *(float4*)&a[0] = *(const float4*)&Ab[k][tm * 4];
            *(float4*)&a[4] = *(const float4*)&Ab[k][64 + tm * 4];
            *(float4*)&b[0] = *(const float4*)&Bb[k][tn * 4];
            *(float4*)&b[4] = *(const float4*)&Bb[k][64 + tn * 4];
            #pragma unroll
            for (int i = 0; i < 8; i++)
                #pragma unroll
                for (int j = 0; j < 8; j++)
                    acc[i][j] = fmaf(a[i], b[j], acc[i][j]);
        }
        __syncthreads();
    }

    #pragma unroll
    for (int ih = 0; ih < 2; ih++) {
        #pragma unroll
        for (int i4 = 0; i4 < 4; i4++) {
            int i = ih * 4 + i4;
            int m = m0 + ih * 64 + tm * 4 + i4;
            #pragma unroll
            for (int jh = 0; jh < 2; jh++) {
                int n = n0 + jh * 64 + tn * 4;
                if (n < N) {
                    float4 v = make_float4(acc[i][jh * 4 + 0], acc[i][jh * 4 + 1],
                                           acc[i][jh * 4 + 2], acc[i][jh * 4 + 3]);
                    if (mode == 1) {
                        float* vv = (float*)&v;
                        #pragma unroll
                        for (int j = 0; j < 4; j++) {
                            float z = vv[j] + bias[n + j];
                            vv[j] = fmaxf(z, 0.f) + log1pf(__expf(-fabsf(z)));
                        }
                    }
                    if (n + 3 < N) {
                        *(float4*)&C[(size_t)m * ldc + n] = v;
                    } else {
                        float* vv = (float*)&v;
                        #pragma unroll
                        for (int j = 0; j < 4; j++)
                            if (n + j < N) C[(size_t)m * ldc + n + j] = vv[j];
                    }
                }
            }
        }
    }
}

// ---------------- depthwise causal conv1d (k=4) + SiLU -> fp16 only ----------------
__global__ __launch_bounds__(256) void conv_silu2_kernel(const float* __restrict__ cw,
                                                         const float* __restrict__ cb,
                                                         const float* __restrict__ xq,
                                                         __half* __restrict__ xch) {
    __shared__ float sx[67][64];
    int d0 = blockIdx.x * 64;
    int mchunk = blockIdx.y;
    int l0 = (mchunk & 63) * 64;
    int b = mchunk >> 6;
    int tid = threadIdx.x;
    int tx = tid & 63, ty = tid >> 6;
    size_t rowbase = (size_t)b * L_SEQ;

    for (int r = ty; r < 67; r += 4) {
        int l = l0 - 3 + r;
        float v = 0.f;
        if (l >= 0) v = xq[(rowbase + l) * D_INNER + d0 + tx];
        sx[r][tx] = v;
    }
    __syncthreads();

    int d = d0 + tx;
    float w0 = cw[d * 4 + 0], w1 = cw[d * 4 + 1];
    float w2 = cw[d * 4 + 2], w3 = cw[d * 4 + 3];
    float bias = cb[d];

    #pragma unroll 4
    for (int i = 0; i < 16; i++) {
        int ll = ty + i * 4;
        int r = ll + 3;
        float acc = bias;
        acc = fmaf(w3, sx[r][tx], acc);
        acc = fmaf(w2, sx[r - 1][tx], acc);
        acc = fmaf(w1, sx[r - 2][tx], acc);
        acc = fmaf(w0, sx[r - 3][tx], acc);
        float sg = 1.f / (1.f + __expf(-acc));
        xch[(rowbase + l0 + ll) * D_INNER + d] = __float2half_rn(acc * sg);
    }
}

// ---------------- selective scan v8: warp-specialized, fp16 x/z inputs ----------------
// 512 threads: warps 0-11 scan, 12-15 reduce. Barrier scheme identical to v7.
#define SCH8 32
#define CH8 24
#define NST8 4
#define NCH8 (L_SEQ / SCH8)     // 128
// float-unit offsets within dynamic smem:
//   sBC  : 4*32*32 f           = [0, 4096)
//   sD   : 4*32*24 f           = [4096, 7168)
//   sXh  : 4*768 halves        = [7168, 8704)
//   sZh  : 4*768 halves        = [8704, 10240)
//   sP   : 2*32*24*20 f        = [10240, 40960)
#define S8_TOTAL 40960   // floats = 163840 B

__global__ __launch_bounds__(512) void scan8_kernel(const float* __restrict__ A_log,
                                                    const float* __restrict__ Dp,
                                                    const float* __restrict__ dtv,
                                                    const __half* __restrict__ xch,
                                                    const float* __restrict__ xdbl,
                                                    const __half* __restrict__ zh,
                                                    __half* __restrict__ yh) {
    extern __shared__ float sm8[];
    float* sBC  = sm8;
    float* sD   = sm8 + 4096;
    __half* sXh = (__half*)(sm8 + 7168);
    __half* sZh = (__half*)(sm8 + 8704);
    float* sP   = sm8 + 10240;

    int b = blockIdx.y;
    int g = blockIdx.x;
    int d0 = g * CH8;
    int tid = threadIdx.x;
    size_t bL = (size_t)b * L_SEQ;

    if (tid < 384) {
        // -------- scan group --------
        int lane = tid & 31;
        int w = tid >> 5;
        int half = lane >> 4;
        int n = lane & 15;
        int dl = 2 * w + half;

        float An = -__expf(A_log[(d0 + dl) * D_STATE + n]);
        float h = 0.f;

        auto issue = [&](int c) {
            int l0 = c * SCH8;
            int buf = c % NST8;
            uint32_t bcs = smem_u32(sBC + buf * 1024);
            uint32_t ds  = smem_u32(sD  + buf * 768);
            uint32_t xs  = smem_u32(sXh + buf * 768);
            uint32_t zs  = smem_u32(sZh + buf * 768);
            for (int u = tid; u < 640; u += 384) {
                if (u < 256) {
                    int l = u >> 3, c4 = u & 7;
                    cpasync16(bcs + (uint32_t)(l * 32 + c4 * 4) * 4,
                              xdbl + (bL + l0 + l) * XPN + DT_RANK + c4 * 4, 16);
                } else if (u < 448) {
                    int v = u - 256; int l = v / 6, c4 = v % 6;
                    cpasync16(ds + (uint32_t)(l * 24 + c4 * 4) * 4,
                              dtv + (bL + l0 + l) * D_INNER + d0 + c4 * 4, 16);
                } else if (u < 544) {
                    int v = u - 448; int l = v / 3, c8 = v % 3;
                    cpasync16(xs + (uint32_t)(l * 24 + c8 * 8) * 2,
                              xch + (bL + l0 + l) * D_INNER + d0 + c8 * 8, 16);
                } else {
                    int v = u - 544; int l = v / 3, c8 = v % 3;
                    cpasync16(zs + (uint32_t)(l * 24 + c8 * 8) * 2,
                              zh + (bL + l0 + l) * D_INNER + d0 + c8 * 8, 16);
                }
            }
            cp_commit();
        };

        issue(0);
        issue(1);

        for (int c = 0; c < NCH8; c++) {
            if (c >= 2) bar_sync(3 + (c & 1), 512);      // reduce(c-2) done
            if (c + 2 < NCH8) { issue(c + 2); cp_wait<2>(); }
            else if (c + 1 < NCH8) { cp_wait<1>(); }
            else { cp_wait<0>(); }
            bar_sync(5, 384);                             // publish stage c%4 to scan group

            int buf = c % NST8;
            const float* bD   = sD  + buf * 768;
            const __half* bX  = sXh + buf * 768;
            const float* bBC  = sBC + buf * 1024;
            float* pS = sP + (c & 1) * 15360;

            #pragma unroll
            for (int s = 0; s < 2; s++) {
                float ev[16], fv[16], cv[16];
                #pragma unroll
                for (int j = 0; j < 16; j++) {
                    int l = s * 16 + j;
                    float dt = bD[l * 24 + dl];
                    float xv = __half2float(bX[l * 24 + dl]);
                    float Bn = bBC[l * 32 + n];
                    cv[j] = bBC[l * 32 + 16 + n];
                    ev[j] = __expf(dt * An);
                    fv[j] = dt * xv * Bn;
                }
                #pragma unroll
                for (int j = 0; j < 16; j++) {
                    h = fmaf(ev[j], h, fv[j]);
                    pS[((s * 16 + j) * 24 + dl) * 20 + n] = h * cv[j];
                }
            }
            bar_arrive(1 + (c & 1), 512);                 // sP[c&1] full
        }
    } else {
        // -------- reduce group (128 threads) --------
        int rt = tid - 384;
        float Dd[6];
        #pragma unroll
        for (int k = 0; k < 6; k++)
            Dd[k] = Dp[d0 + (rt + 128 * k) % 24];

        for (int c = 0; c < NCH8; c++) {
            bar_sync(1 + (c & 1), 512);                   // wait sP[c&1] full
            int buf = c % NST8;
            const __half* bX = sXh + buf * 768;
            const __half* bZ = sZh + buf * 768;
            const float* pS = sP + (c & 1) * 15360;

            #pragma unroll
            for (int k = 0; k < 6; k++) {
                int u = rt + 128 * k;
                const float* p = pS + u * 20;
                float4 a  = *(const float4*)p;
                float4 bq = *(const float4*)(p + 4);
                float4 cq = *(const float4*)(p + 8);
                float4 dq = *(const float4*)(p + 12);
                float s = ((a.x + a.y) + (a.z + a.w)) + ((bq.x + bq.y) + (bq.z + bq.w))
                        + ((cq.x + cq.y) + (cq.z + cq.w)) + ((dq.x + dq.y) + (dq.z + dq.w));
                float xv = __half2float(bX[u]);
                float zv = __half2float(bZ[u]);
                float yv = fmaf(xv, Dd[k], s);
                yv *= zv / (1.f + __expf(-zv));
                int l = u / 24, ch = u % 24;
                yh[(bL + (size_t)c * SCH8 + l) * D_INNER + d0 + ch] = __float2half_rn(yv);
            }
            bar_arrive(3 + (c & 1), 512);                 // chunk c consumed
        }
    }
}

// ---------------- launch ----------------
extern "C" void kernel_launch(void* const* d_in, const int* in_sizes, int n_in,
                              void* d_out, int out_size) {
    const float* x          = (const float*)d_in[0];
    const float* ln_w       = (const float*)d_in[1];
    const float* ln_b       = (const float*)d_in[2];
    const float* in_proj_w  = (const float*)d_in[3];
    const float* conv_w     = (const float*)d_in[4];
    const float* conv_b     = (const float*)d_in[5];
    const float* x_proj_w   = (const float*)d_in[6];
    const float* dt_w       = (const float*)d_in[7];
    const float* dt_b       = (const float*)d_in[8];
    const float* A_log      = (const float*)d_in[9];
    const float* Dp         = (const float*)d_in[10];
    const float* out_proj_w = (const float*)d_in[11];
    float* out = (float*)d_out;

    float *p_xq, *p_xdbl, *p_dtv;
    __half *p_zh, *p_xnh, *p_xch, *p_yh;
    __half *p_wih, *p_wil, *p_woh, *p_wol, *p_wxh, *p_wxl;
    cudaGetSymbolAddress((void**)&p_xq,   g_xq);
    cudaGetSymbolAddress((void**)&p_xdbl, g_xdbl);
    cudaGetSymbolAddress((void**)&p_dtv,  g_dtv);
    cudaGetSymbolAddress((void**)&p_zh,   g_z_h);
    cudaGetSymbolAddress((void**)&p_xnh,  g_xn_h);
    cudaGetSymbolAddress((void**)&p_xch,  g_xc_h);
    cudaGetSymbolAddress((void**)&p_yh,   g_y_h);
    cudaGetSymbolAddress((void**)&p_wih,  g_wi_hi);
    cudaGetSymbolAddress((void**)&p_wil,  g_wi_lo);
    cudaGetSymbolAddress((void**)&p_woh,  g_wo_hi);
    cudaGetSymbolAddress((void**)&p_wol,  g_wo_lo);
    cudaGetSymbolAddress((void**)&p_wxh,  g_wx_hi);
    cudaGetSymbolAddress((void**)&p_wxl,  g_wx_lo);

    const int SC_SMEM = S8_TOTAL * 4;   // 163840 B
    cudaFuncSetAttribute(mmagemm_kernel, cudaFuncAttributeMaxDynamicSharedMemorySize, MM_SMEM);
    cudaFuncSetAttribute(scan8_kernel, cudaFuncAttributeMaxDynamicSharedMemorySize, SC_SMEM);

    // 0) weight hi/lo conversion (single launch)
    int n4i = (2 * D_INNER * DIMC) / 4;
    int n4o = (DIMC * D_INNER) / 4;
    int n4x = (XPN * D_INNER) / 4;
    cvt3_kernel<<<(n4i + n4o + n4x + 255) / 256, 256>>>(
        in_proj_w, p_wih, p_wil, n4i,
        out_proj_w, p_woh, p_wol, n4o,
        x_proj_w, p_wxh, p_wxl, n4x);

    // 1) LayerNorm -> xn fp16
    ln_kernel<<<dim3(L_SEQ / 64, B_SZ), 256>>>(x, ln_w, ln_b, p_xnh);

    // 2) in_proj (fp16 2-term), split store: x-half fp32 -> xq, z-half fp16 -> zh
    mmagemm_kernel<<<dim3(2 * D_INNER / 128, M_TOTAL / 128), 256, MM_SMEM>>>(
        p_xnh, p_wih, p_wil, DIMC, 2 * D_INNER, p_xq, p_zh, 0, 3);

    // 3) depthwise conv + silu -> xc fp16
    conv_silu2_kernel<<<dim3(D_INNER / 64, M_TOTAL / 64), 256>>>(
        conv_w, conv_b, p_xq, p_xch);

    // 4) x_proj (fp16 2-term, N=56 masked)
    mmagemm_kernel<<<dim3(1, M_TOTAL / 128), 256, MM_SMEM>>>(
        p_xch, p_wxh, p_wxl, D_INNER, XPN, p_xdbl, nullptr, XPN, 0);

    // 5) dt + softplus (fp32 SIMT, K=24)
    gemm2_kernel<<<dim3(D_INNER / BN, M_TOTAL / BM), 256>>>(
        p_xdbl, XPN, DT_RANK, dt_w, DT_RANK, D_INNER, p_dtv, D_INNER, 1, dt_b);

    // 6) selective scan v8 (warp-specialized, fp16 x/z) -> y fp16
    scan8_kernel<<<dim3(D_INNER / CH8, B_SZ), 512, SC_SMEM>>>(
        A_log, Dp, p_dtv, p_xch, p_xdbl, p_zh, p_yh);

    // 7) out_proj (fp16 2-term, transposed store)
    mmagemm_kernel<<<dim3(DIMC / 128, M_TOTAL / 128), 256, MM_SMEM>>>(
        p_yh, p_woh, p_wol, D_INNER, DIMC, out, nullptr, 0, 2);
}